// round 4
// baseline (speedup 1.0000x reference)
#include <cuda_runtime.h>
#include <math.h>

// ---------------- problem constants ----------------
#define SQ 2048      // sequence
#define HD 2048      // hidden
#define NHD 16       // heads
#define DH 128       // head dim
#define NE 8         // experts
#define NTOP 4       // top-k
#define IEX 1408     // expert intermediate
#define ISH 5632     // shared intermediate

// ---------------- scratch (device globals; no allocs allowed) ----------------
__device__ float g_h[SQ * HD];       // normalized hidden (ln1 then ln2 outputs)
__device__ float g_q[SQ * HD];
__device__ float g_k[SQ * HD];
__device__ float g_v[SQ * HD];
__device__ float g_attn[SQ * HD];
__device__ float g_x1[SQ * HD];      // x + attn@wo
__device__ float g_moe[SQ * HD];     // MoE accumulator (zeroed each launch)
__device__ float g_sh[SQ * ISH];     // shared-expert gate then gup
__device__ float g_eup[SQ * IEX];    // single expert buffer (experts sequential)
__device__ float g_w[SQ * NE];       // dense routing weights
__device__ float g_sig[SQ];          // shared gate sigmoid
__device__ int   g_rows[NE * SQ];    // per-expert compacted token lists
__device__ int   g_cnt[NE];          // per-expert token counts

// ---------------- init ----------------
__global__ void k_zero(float* moe, int n, int* cnt) {
    int i = blockIdx.x * blockDim.x + threadIdx.x;
    int stride = gridDim.x * blockDim.x;
    for (; i < n; i += stride) moe[i] = 0.f;
    if (blockIdx.x == 0 && threadIdx.x < NE) cnt[threadIdx.x] = 0;
}

// ---------------- RMSNorm ----------------
__global__ __launch_bounds__(256) void k_rmsnorm(const float* __restrict__ x,
                                                 const float* __restrict__ w,
                                                 float* __restrict__ out) {
    int r = blockIdx.x, tid = threadIdx.x;
    const float* xr = x + (size_t)r * HD;
    float s = 0.f;
    for (int i = tid; i < HD; i += 256) { float v = xr[i]; s += v * v; }
    for (int o = 16; o; o >>= 1) s += __shfl_down_sync(0xFFFFFFFFu, s, o);
    __shared__ float red[8];
    __shared__ float rs_sh;
    if ((tid & 31) == 0) red[tid >> 5] = s;
    __syncthreads();
    if (tid == 0) {
        float t = 0.f;
        for (int i = 0; i < 8; i++) t += red[i];
        rs_sh = rsqrtf(t / (float)HD + 1e-6f);
    }
    __syncthreads();
    float rs = rs_sh;
    float* orow = out + (size_t)r * HD;
    for (int i = tid; i < HD; i += 256) orow[i] = w[i] * xr[i] * rs;
}

// ---------------- RoPE (in-place on q and k) ----------------
__global__ void k_rope(float* __restrict__ q, float* __restrict__ k) {
    int s = blockIdx.x, h = blockIdx.y, d = threadIdx.x; // d in [0,64)
    float inv = 1.0f / powf(1.0e6f, (float)d / 64.0f);
    float ang = (float)s * inv;
    float sn, c;
    sincosf(ang, &sn, &c);
    size_t b = (size_t)s * HD + (size_t)h * DH;
    float q1 = q[b + d], q2 = q[b + d + 64];
    q[b + d]      = q1 * c - q2 * sn;
    q[b + d + 64] = q2 * c + q1 * sn;
    float k1 = k[b + d], k2 = k[b + d + 64];
    k[b + d]      = k1 * c - k2 * sn;
    k[b + d + 64] = k2 * c + k1 * sn;
}

// ---------------- flash attention (fp32, causal) ----------------
// Br=32, Bc=32. 8 warps: warp w owns q rows w*4..w*4+3; lane = k column.
// K stored row-padded to 129 floats (conflict-free column reads);
// V re-stored in the SAME buffer, row-major stride 128 (float4 reads).
// Static smem: 16KB (Q) + 16.5KB (KV) + 4KB (P) = 36.6KB -> no attr calls.
__global__ __launch_bounds__(256) void k_attn(const float* __restrict__ Q,
                                              const float* __restrict__ Km,
                                              const float* __restrict__ Vm,
                                              float* __restrict__ O) {
    __shared__ float Qs[32 * 128];
    __shared__ float KV[32 * 129];
    __shared__ float Ps[32 * 32];
    int qt = blockIdx.x, h = blockIdx.y, tid = threadIdx.x;
    int warp = tid >> 5, lane = tid & 31;
    int qs = qt * 32;
    int q0 = warp * 4;

    for (int idx = tid; idx < 32 * 32; idx += 256) {
        int r = idx >> 5, c4 = (idx & 31) * 4;
        *(float4*)&Qs[r * 128 + c4] =
            *(const float4*)&Q[(size_t)(qs + r) * HD + (size_t)h * DH + c4];
    }

    float mi[4], li[4], o[4][4];
#pragma unroll
    for (int i = 0; i < 4; i++) {
        mi[i] = -INFINITY; li[i] = 0.f;
        o[i][0] = o[i][1] = o[i][2] = o[i][3] = 0.f;
    }
    const float scale = 0.08838834764831845f; // 1/sqrt(128)

    for (int kt = 0; kt <= qt; kt++) {
        int ks = kt * 32;
        __syncthreads();
        // K tile, rows padded to 129
        for (int idx = tid; idx < 32 * 32; idx += 256) {
            int r = idx >> 5, c4 = (idx & 31) * 4;
            float4 kv = *(const float4*)&Km[(size_t)(ks + r) * HD + (size_t)h * DH + c4];
            float* dst = &KV[r * 129 + c4];
            dst[0] = kv.x; dst[1] = kv.y; dst[2] = kv.z; dst[3] = kv.w;
        }
        __syncthreads();

        // S = Q K^T for my 4 rows x my 1 column (lane)
        float s[4] = {0.f, 0.f, 0.f, 0.f};
        const float* krow = &KV[lane * 129];
        for (int d = 0; d < 128; d += 4) {
            float k0 = krow[d], k1 = krow[d + 1], k2 = krow[d + 2], k3 = krow[d + 3];
#pragma unroll
            for (int i = 0; i < 4; i++) {
                float4 qv = *(float4*)&Qs[(q0 + i) * 128 + d];
                s[i] += qv.x * k0 + qv.y * k1 + qv.z * k2 + qv.w * k3;
            }
        }
#pragma unroll
        for (int i = 0; i < 4; i++) {
            s[i] *= scale;
            if (kt == qt && lane > q0 + i) s[i] = -INFINITY;
        }

        // online softmax update (warp-wide per row)
#pragma unroll
        for (int i = 0; i < 4; i++) {
            float mx = s[i];
            for (int off = 16; off; off >>= 1)
                mx = fmaxf(mx, __shfl_xor_sync(0xFFFFFFFFu, mx, off));
            float mn = fmaxf(mi[i], mx);
            float alpha = expf(mi[i] - mn);
            float pv = expf(s[i] - mn);
            Ps[(q0 + i) * 32 + lane] = pv;
            float ls = pv;
            for (int off = 16; off; off >>= 1)
                ls += __shfl_xor_sync(0xFFFFFFFFu, ls, off);
            li[i] = li[i] * alpha + ls;
            mi[i] = mn;
            o[i][0] *= alpha; o[i][1] *= alpha; o[i][2] *= alpha; o[i][3] *= alpha;
        }
        __syncthreads();

        // V tile, row-major stride 128 (overwrites K region)
        for (int idx = tid; idx < 32 * 32; idx += 256) {
            int r = idx >> 5, c4 = (idx & 31) * 4;
            *(float4*)&KV[r * 128 + c4] =
                *(const float4*)&Vm[(size_t)(ks + r) * HD + (size_t)h * DH + c4];
        }
        __syncthreads();

        // O += P V  (lane owns d columns lane*4..lane*4+3)
        for (int kk = 0; kk < 32; kk++) {
            float4 vv = *(float4*)&KV[kk * 128 + lane * 4];
#pragma unroll
            for (int i = 0; i < 4; i++) {
                float p = Ps[(q0 + i) * 32 + kk];
                o[i][0] += p * vv.x; o[i][1] += p * vv.y;
                o[i][2] += p * vv.z; o[i][3] += p * vv.w;
            }
        }
    }

#pragma unroll
    for (int i = 0; i < 4; i++) {
        float r = 1.f / li[i];
        size_t base = (size_t)(qs + q0 + i) * HD + (size_t)h * DH + lane * 4;
        O[base + 0] = o[i][0] * r; O[base + 1] = o[i][1] * r;
        O[base + 2] = o[i][2] * r; O[base + 3] = o[i][3] * r;
    }
}

// ---------------- generic tiled SGEMM with epilogues ----------------
// C = A(MxK) @ B(KxN), all row-major; 128x128x8 tile, 8x8 per thread.
enum { EPI_STORE = 0, EPI_SILU_MUL = 1, EPI_ADD_RES = 2, EPI_MOE_SCATTER = 3, EPI_FINAL = 4 };

template <int EPI, bool GATHER>
__global__ __launch_bounds__(256) void k_gemm(
    const float* __restrict__ A, const float* __restrict__ B, float* __restrict__ C,
    int M, int N, int K,
    const float* __restrict__ bias,
    const float* __restrict__ res,
    const int* __restrict__ rowIdx, const int* __restrict__ rowCnt,
    const float* __restrict__ wvec, int expertId,
    const float* __restrict__ sig, const float* __restrict__ moe) {
    int Mc = rowCnt ? *rowCnt : M;
    int m0 = blockIdx.y * 128;
    if (m0 >= Mc) return;
    int n0 = blockIdx.x * 128;

    __shared__ float As[8][128];
    __shared__ float Bs[8][128];

    int tid = threadIdx.x;
    int tx = tid & 15, ty = tid >> 4;

    int lr = tid >> 1, lc = (tid & 1) * 4;
    int mA = m0 + lr; if (mA > Mc - 1) mA = Mc - 1;
    const float* aSrc = A + (size_t)(GATHER ? rowIdx[mA] : mA) * K + lc;
    int lrb = tid >> 5, lcb = (tid & 31) * 4;
    const float* bSrc = B + (size_t)lrb * N + n0 + lcb;

    float acc[8][8];
#pragma unroll
    for (int i = 0; i < 8; i++)
#pragma unroll
        for (int j = 0; j < 8; j++) acc[i][j] = 0.f;

    for (int k0 = 0; k0 < K; k0 += 8) {
        float4 av = *(const float4*)(aSrc + k0);
        float4 bv = *(const float4*)(bSrc + (size_t)k0 * N);
        __syncthreads();
        As[lc + 0][lr] = av.x; As[lc + 1][lr] = av.y;
        As[lc + 2][lr] = av.z; As[lc + 3][lr] = av.w;
        *(float4*)&Bs[lrb][lcb] = bv;
        __syncthreads();
#pragma unroll
        for (int kk = 0; kk < 8; kk++) {
            float a[8], b[8];
            *(float4*)(a)     = *(const float4*)&As[kk][ty * 8];
            *(float4*)(a + 4) = *(const float4*)&As[kk][ty * 8 + 4];
            *(float4*)(b)     = *(const float4*)&Bs[kk][tx * 8];
            *(float4*)(b + 4) = *(const float4*)&Bs[kk][tx * 8 + 4];
#pragma unroll
            for (int i = 0; i < 8; i++)
#pragma unroll
                for (int j = 0; j < 8; j++) acc[i][j] += a[i] * b[j];
        }
    }

#pragma unroll
    for (int i = 0; i < 8; i++) {
        int m = m0 + ty * 8 + i;
        if (m >= Mc) break;
        int nb = n0 + tx * 8;
        if (EPI == EPI_MOE_SCATTER) {
            int tok = rowIdx[m];
            float wv = wvec[tok * NE + expertId];
            float* crow = C + (size_t)tok * N + nb;
#pragma unroll
            for (int j = 0; j < 8; j++) crow[j] += wv * acc[i][j];
        } else {
            float* crow = C + (size_t)m * N + nb;
#pragma unroll
            for (int j = 0; j < 8; j++) {
                float v = acc[i][j];
                if (EPI == EPI_STORE) {
                    if (bias) v += bias[nb + j];
                    crow[j] = v;
                } else if (EPI == EPI_SILU_MUL) {
                    float g = crow[j];
                    crow[j] = (g / (1.f + expf(-g))) * v;
                } else if (EPI == EPI_ADD_RES) {
                    crow[j] = res[(size_t)m * N + nb + j] + v;
                } else if (EPI == EPI_FINAL) {
                    size_t idx = (size_t)m * N + nb + j;
                    crow[j] = res[idx] + moe[idx] + sig[m] * v;
                }
            }
        }
    }
}

// ---------------- router: logits + softmax + top-4 + compaction ----------------
__global__ __launch_bounds__(256) void k_router(const float* __restrict__ h,
                                                const float* __restrict__ gw,
                                                float* __restrict__ logits_out,
                                                float* __restrict__ wout,
                                                int* __restrict__ cnt,
                                                int* __restrict__ rows) {
    int t = blockIdx.x, tid = threadIdx.x;
    const float* hr = h + (size_t)t * HD;
    float p[NE];
#pragma unroll
    for (int e = 0; e < NE; e++) p[e] = 0.f;
    for (int i = tid; i < HD; i += 256) {
        float hv = hr[i];
        const float* g = gw + (size_t)i * NE;
#pragma unroll
        for (int e = 0; e < NE; e++) p[e] += hv * g[e];
    }
    for (int off = 16; off; off >>= 1)
#pragma unroll
        for (int e = 0; e < NE; e++) p[e] += __shfl_down_sync(0xFFFFFFFFu, p[e], off);
    __shared__ float smr[8][NE];
    int w = tid >> 5;
    if ((tid & 31) == 0)
#pragma unroll
        for (int e = 0; e < NE; e++) smr[w][e] = p[e];
    __syncthreads();
    if (tid == 0) {
        float l[NE];
#pragma unroll
        for (int e = 0; e < NE; e++) {
            float s = 0.f;
            for (int ww = 0; ww < 8; ww++) s += smr[ww][e];
            l[e] = s;
            logits_out[(size_t)t * NE + e] = s;
        }
        float mx = l[0];
#pragma unroll
        for (int e = 1; e < NE; e++) mx = fmaxf(mx, l[e]);
        float den = 0.f, r[NE];
#pragma unroll
        for (int e = 0; e < NE; e++) { r[e] = expf(l[e] - mx); den += r[e]; }
#pragma unroll
        for (int e = 0; e < NE; e++) r[e] /= den;
        bool used[NE];
#pragma unroll
        for (int e = 0; e < NE; e++) used[e] = false;
        float wrow[NE];
#pragma unroll
        for (int e = 0; e < NE; e++) wrow[e] = 0.f;
        for (int kk = 0; kk < NTOP; kk++) {
            int bi = -1; float bv = -1.f;
            for (int e = 0; e < NE; e++)
                if (!used[e] && r[e] > bv) { bv = r[e]; bi = e; }
            used[bi] = true;
            wrow[bi] = bv;
            int pos = atomicAdd(&cnt[bi], 1);
            rows[bi * SQ + pos] = t;
        }
#pragma unroll
        for (int e = 0; e < NE; e++) wout[t * NE + e] = wrow[e];
    }
}

// ---------------- shared gate (sigmoid(h @ sgate)) ----------------
__global__ __launch_bounds__(256) void k_sgate(const float* __restrict__ h,
                                               const float* __restrict__ sgw,
                                               float* __restrict__ sig) {
    int t = blockIdx.x, tid = threadIdx.x;
    const float* hr = h + (size_t)t * HD;
    float s = 0.f;
    for (int i = tid; i < HD; i += 256) s += hr[i] * sgw[i];
    for (int off = 16; off; off >>= 1) s += __shfl_down_sync(0xFFFFFFFFu, s, off);
    __shared__ float red[8];
    if ((tid & 31) == 0) red[tid >> 5] = s;
    __syncthreads();
    if (tid == 0) {
        float tot = 0.f;
        for (int i = 0; i < 8; i++) tot += red[i];
        sig[t] = 1.f / (1.f + expf(-tot));
    }
}

// ---------------- launch ----------------
extern "C" void kernel_launch(void* const* d_in, const int* in_sizes, int n_in,
                              void* d_out, int out_size) {
    const float* x     = (const float*)d_in[0];
    const float* ln1   = (const float*)d_in[1];
    const float* ln2   = (const float*)d_in[2];
    const float* wq    = (const float*)d_in[3];
    const float* bq    = (const float*)d_in[4];
    const float* wk    = (const float*)d_in[5];
    const float* bk    = (const float*)d_in[6];
    const float* wv    = (const float*)d_in[7];
    const float* bv    = (const float*)d_in[8];
    const float* wo    = (const float*)d_in[9];
    const float* gatew = (const float*)d_in[10];
    const float* eg    = (const float*)d_in[11];
    const float* eu    = (const float*)d_in[12];
    const float* ed    = (const float*)d_in[13];
    const float* sgw   = (const float*)d_in[14];
    const float* suw   = (const float*)d_in[15];
    const float* sdw   = (const float*)d_in[16];
    const float* sgate = (const float*)d_in[17];
    float* out = (float*)d_out;

    float *h, *q, *k, *v, *attn, *x1, *moe, *sh, *eup, *w, *sig;
    int *rows, *cnt;
    cudaGetSymbolAddress((void**)&h, g_h);
    cudaGetSymbolAddress((void**)&q, g_q);
    cudaGetSymbolAddress((void**)&k, g_k);
    cudaGetSymbolAddress((void**)&v, g_v);
    cudaGetSymbolAddress((void**)&attn, g_attn);
    cudaGetSymbolAddress((void**)&x1, g_x1);
    cudaGetSymbolAddress((void**)&moe, g_moe);
    cudaGetSymbolAddress((void**)&sh, g_sh);
    cudaGetSymbolAddress((void**)&eup, g_eup);
    cudaGetSymbolAddress((void**)&w, g_w);
    cudaGetSymbolAddress((void**)&sig, g_sig);
    cudaGetSymbolAddress((void**)&rows, g_rows);
    cudaGetSymbolAddress((void**)&cnt, g_cnt);

    // 0. reset accumulators (inside the graph so replays are idempotent)
    k_zero<<<256, 256>>>(moe, SQ * HD, cnt);

    // 1. ln1
    k_rmsnorm<<<SQ, 256>>>(x, ln1, h);

    // 2. qkv
    dim3 g16(HD / 128, SQ / 128);
    k_gemm<EPI_STORE, false><<<g16, 256>>>(h, wq, q, SQ, HD, HD, bq, nullptr, nullptr, nullptr, nullptr, 0, nullptr, nullptr);
    k_gemm<EPI_STORE, false><<<g16, 256>>>(h, wk, k, SQ, HD, HD, bk, nullptr, nullptr, nullptr, nullptr, 0, nullptr, nullptr);
    k_gemm<EPI_STORE, false><<<g16, 256>>>(h, wv, v, SQ, HD, HD, bv, nullptr, nullptr, nullptr, nullptr, 0, nullptr, nullptr);

    // 3. rope
    k_rope<<<dim3(SQ, NHD), 64>>>(q, k);

    // 4. attention (static smem only; 64 q-tiles x 16 heads)
    k_attn<<<dim3(SQ / 32, NHD), 256>>>(q, k, v, attn);

    // 5. x1 = x + attn @ wo
    k_gemm<EPI_ADD_RES, false><<<g16, 256>>>(attn, wo, x1, SQ, HD, HD, nullptr, x, nullptr, nullptr, nullptr, 0, nullptr, nullptr);

    // 6. ln2
    k_rmsnorm<<<SQ, 256>>>(x1, ln2, h);

    // 7. router (+logits to output tail) and shared gate
    k_router<<<SQ, 256>>>(h, gatew, out + (size_t)SQ * HD, w, cnt, rows);
    k_sgate<<<SQ, 256>>>(h, sgate, sig);

    // 8. MoE experts (sparse via compaction; sequential per-expert, shared eup buffer)
    for (int e = 0; e < NE; e++) {
        dim3 ge(IEX / 128, SQ / 128);
        k_gemm<EPI_STORE, true><<<ge, 256>>>(h, eg + (size_t)e * HD * IEX, eup,
            SQ, IEX, HD, nullptr, nullptr, rows + e * SQ, cnt + e, nullptr, 0, nullptr, nullptr);
        k_gemm<EPI_SILU_MUL, true><<<ge, 256>>>(h, eu + (size_t)e * HD * IEX, eup,
            SQ, IEX, HD, nullptr, nullptr, rows + e * SQ, cnt + e, nullptr, 0, nullptr, nullptr);
        k_gemm<EPI_MOE_SCATTER, false><<<g16, 256>>>(eup, ed + (size_t)e * IEX * HD, moe,
            SQ, HD, IEX, nullptr, nullptr, rows + e * SQ, cnt + e, w, e, nullptr, nullptr);
    }

    // 9. shared expert
    dim3 gs(ISH / 128, SQ / 128);
    k_gemm<EPI_STORE, false><<<gs, 256>>>(h, sgw, sh, SQ, ISH, HD, nullptr, nullptr, nullptr, nullptr, nullptr, 0, nullptr, nullptr);
    k_gemm<EPI_SILU_MUL, false><<<gs, 256>>>(h, suw, sh, SQ, ISH, HD, nullptr, nullptr, nullptr, nullptr, nullptr, 0, nullptr, nullptr);

    // 10. final: out = x1 + moe + sig * (sh @ sd)
    k_gemm<EPI_FINAL, false><<<g16, 256>>>(sh, sdw, out, SQ, HD, ISH, nullptr, x1, nullptr, nullptr, nullptr, 0, sig, moe);
}

// round 5
// speedup vs baseline: 1.4589x; 1.4589x over previous
#include <cuda_runtime.h>
#include <math.h>

// ---------------- problem constants ----------------
#define SQ 2048      // sequence
#define HD 2048      // hidden
#define NHD 16       // heads
#define DH 128       // head dim
#define NE 8         // experts
#define NTOP 4       // top-k
#define IEX 1408     // expert intermediate
#define ISH 5632     // shared intermediate

// ---------------- scratch (device globals; no allocs allowed) ----------------
__device__ float g_h[SQ * HD];        // normalized hidden (ln1 then ln2 outputs)
__device__ float g_q[SQ * HD];
__device__ float g_k[SQ * HD];
__device__ float g_v[SQ * HD];
__device__ float g_attn[SQ * HD];
__device__ float g_x1[SQ * HD];       // x + attn@wo
__device__ float g_moe[SQ * HD];      // combined MoE output (fully overwritten)
__device__ float g_sh[SQ * ISH];      // shared-expert gate then gup
__device__ float g_eup[NE * SQ * IEX];   // per-expert compacted gate/up
__device__ float g_edown[NE * SQ * HD];  // per-expert compacted down output
__device__ float g_w[SQ * NE];        // dense routing weights (0 if unselected)
__device__ float g_sig[SQ];           // shared gate sigmoid
__device__ int   g_rows[NE * SQ];     // per-expert compacted token lists
__device__ int   g_pos[SQ * NE];      // token -> position in expert's compacted list
__device__ int   g_cnt[NE];           // per-expert token counts

// ---------------- init (counters only) ----------------
__global__ void k_zero_cnt(int* cnt) {
    if (threadIdx.x < NE) cnt[threadIdx.x] = 0;
}

// ---------------- RMSNorm ----------------
__global__ __launch_bounds__(256) void k_rmsnorm(const float* __restrict__ x,
                                                 const float* __restrict__ w,
                                                 float* __restrict__ out) {
    int r = blockIdx.x, tid = threadIdx.x;
    const float* xr = x + (size_t)r * HD;
    float s = 0.f;
    for (int i = tid; i < HD; i += 256) { float v = xr[i]; s += v * v; }
    for (int o = 16; o; o >>= 1) s += __shfl_down_sync(0xFFFFFFFFu, s, o);
    __shared__ float red[8];
    __shared__ float rs_sh;
    if ((tid & 31) == 0) red[tid >> 5] = s;
    __syncthreads();
    if (tid == 0) {
        float t = 0.f;
        for (int i = 0; i < 8; i++) t += red[i];
        rs_sh = rsqrtf(t / (float)HD + 1e-6f);
    }
    __syncthreads();
    float rs = rs_sh;
    float* orow = out + (size_t)r * HD;
    for (int i = tid; i < HD; i += 256) orow[i] = w[i] * xr[i] * rs;
}

// ---------------- RoPE (in-place on q and k) ----------------
__global__ void k_rope(float* __restrict__ q, float* __restrict__ k) {
    int s = blockIdx.x, h = blockIdx.y, d = threadIdx.x; // d in [0,64)
    float inv = 1.0f / powf(1.0e6f, (float)d / 64.0f);
    float ang = (float)s * inv;
    float sn, c;
    sincosf(ang, &sn, &c);
    size_t b = (size_t)s * HD + (size_t)h * DH;
    float q1 = q[b + d], q2 = q[b + d + 64];
    q[b + d]      = q1 * c - q2 * sn;
    q[b + d + 64] = q2 * c + q1 * sn;
    float k1 = k[b + d], k2 = k[b + d + 64];
    k[b + d]      = k1 * c - k2 * sn;
    k[b + d + 64] = k2 * c + k1 * sn;
}

// ---------------- flash attention (fp32, causal) ----------------
__global__ __launch_bounds__(256) void k_attn(const float* __restrict__ Q,
                                              const float* __restrict__ Km,
                                              const float* __restrict__ Vm,
                                              float* __restrict__ O) {
    __shared__ float Qs[32 * 128];
    __shared__ float KV[32 * 129];
    __shared__ float Ps[32 * 32];
    int qt = blockIdx.x, h = blockIdx.y, tid = threadIdx.x;
    int warp = tid >> 5, lane = tid & 31;
    int qs = qt * 32;
    int q0 = warp * 4;

    for (int idx = tid; idx < 32 * 32; idx += 256) {
        int r = idx >> 5, c4 = (idx & 31) * 4;
        *(float4*)&Qs[r * 128 + c4] =
            *(const float4*)&Q[(size_t)(qs + r) * HD + (size_t)h * DH + c4];
    }

    float mi[4], li[4], o[4][4];
#pragma unroll
    for (int i = 0; i < 4; i++) {
        mi[i] = -INFINITY; li[i] = 0.f;
        o[i][0] = o[i][1] = o[i][2] = o[i][3] = 0.f;
    }
    const float scale = 0.08838834764831845f; // 1/sqrt(128)

    for (int kt = 0; kt <= qt; kt++) {
        int ks = kt * 32;
        __syncthreads();
        for (int idx = tid; idx < 32 * 32; idx += 256) {
            int r = idx >> 5, c4 = (idx & 31) * 4;
            float4 kv = *(const float4*)&Km[(size_t)(ks + r) * HD + (size_t)h * DH + c4];
            float* dst = &KV[r * 129 + c4];
            dst[0] = kv.x; dst[1] = kv.y; dst[2] = kv.z; dst[3] = kv.w;
        }
        __syncthreads();

        float s[4] = {0.f, 0.f, 0.f, 0.f};
        const float* krow = &KV[lane * 129];
        for (int d = 0; d < 128; d += 4) {
            float k0 = krow[d], k1 = krow[d + 1], k2 = krow[d + 2], k3 = krow[d + 3];
#pragma unroll
            for (int i = 0; i < 4; i++) {
                float4 qv = *(float4*)&Qs[(q0 + i) * 128 + d];
                s[i] += qv.x * k0 + qv.y * k1 + qv.z * k2 + qv.w * k3;
            }
        }
#pragma unroll
        for (int i = 0; i < 4; i++) {
            s[i] *= scale;
            if (kt == qt && lane > q0 + i) s[i] = -INFINITY;
        }

#pragma unroll
        for (int i = 0; i < 4; i++) {
            float mx = s[i];
            for (int off = 16; off; off >>= 1)
                mx = fmaxf(mx, __shfl_xor_sync(0xFFFFFFFFu, mx, off));
            float mn = fmaxf(mi[i], mx);
            float alpha = expf(mi[i] - mn);
            float pv = expf(s[i] - mn);
            Ps[(q0 + i) * 32 + lane] = pv;
            float ls = pv;
            for (int off = 16; off; off >>= 1)
                ls += __shfl_xor_sync(0xFFFFFFFFu, ls, off);
            li[i] = li[i] * alpha + ls;
            mi[i] = mn;
            o[i][0] *= alpha; o[i][1] *= alpha; o[i][2] *= alpha; o[i][3] *= alpha;
        }
        __syncthreads();

        for (int idx = tid; idx < 32 * 32; idx += 256) {
            int r = idx >> 5, c4 = (idx & 31) * 4;
            *(float4*)&KV[r * 128 + c4] =
                *(const float4*)&Vm[(size_t)(ks + r) * HD + (size_t)h * DH + c4];
        }
        __syncthreads();

        for (int kk = 0; kk < 32; kk++) {
            float4 vv = *(float4*)&KV[kk * 128 + lane * 4];
#pragma unroll
            for (int i = 0; i < 4; i++) {
                float p = Ps[(q0 + i) * 32 + kk];
                o[i][0] += p * vv.x; o[i][1] += p * vv.y;
                o[i][2] += p * vv.z; o[i][3] += p * vv.w;
            }
        }
    }

#pragma unroll
    for (int i = 0; i < 4; i++) {
        float r = 1.f / li[i];
        size_t base = (size_t)(qs + q0 + i) * HD + (size_t)h * DH + lane * 4;
        O[base + 0] = o[i][0] * r; O[base + 1] = o[i][1] * r;
        O[base + 2] = o[i][2] * r; O[base + 3] = o[i][3] * r;
    }
}

// ---------------- double-buffered tiled SGEMM with epilogues ----------------
// C = A(MxK) @ B(KxN), row-major; 128x128x16 tile, 8x8 per thread, 256 thr.
enum { EPI_STORE = 0, EPI_SILU_MUL = 1, EPI_ADD_RES = 2, EPI_FINAL = 3 };

template <int EPI, bool GATHER, bool FUSEZ>
__global__ __launch_bounds__(256) void k_gemm(
    const float* __restrict__ A, const float* __restrict__ B, float* __restrict__ C,
    int M, int N, int K,
    const float* __restrict__ bias,
    const float* __restrict__ res,
    const int* __restrict__ rowIdx, const int* __restrict__ rowCnt,
    const float* __restrict__ sig, const float* __restrict__ moe,
    size_t zsA, size_t zsB, size_t zsC) {
    if (FUSEZ) {
        int z = blockIdx.z;
        A += (size_t)z * zsA; B += (size_t)z * zsB; C += (size_t)z * zsC;
        rowIdx += z * SQ; rowCnt += z;
    }
    int Mc = rowCnt ? *rowCnt : M;
    int m0 = blockIdx.y * 128;
    if (m0 >= Mc) return;
    int n0 = blockIdx.x * 128;

    __shared__ float As[2][16][128];
    __shared__ float Bs[2][16][128];

    int tid = threadIdx.x;
    int tx = tid & 15, ty = tid >> 4;

    // A loader: 128 rows x 16 cols; thread -> (row=tid>>1, col=(tid&1)*8), 2x float4
    int aRow = tid >> 1, aCol = (tid & 1) * 8;
    int mA = m0 + aRow; if (mA > Mc - 1) mA = Mc - 1;
    const float* aSrc = A + (size_t)(GATHER ? rowIdx[mA] : mA) * K + aCol;
    // B loader: 16 rows x 128 cols; thread -> (row=tid>>4, col=(tid&15)*8), 2x float4
    int bRow = tid >> 4, bCol = (tid & 15) * 8;
    const float* bSrc = B + (size_t)bRow * N + n0 + bCol;

    float acc[8][8];
#pragma unroll
    for (int i = 0; i < 8; i++)
#pragma unroll
        for (int j = 0; j < 8; j++) acc[i][j] = 0.f;

    float4 av0, av1, bv0, bv1;
    av0 = *(const float4*)(aSrc);
    av1 = *(const float4*)(aSrc + 4);
    bv0 = *(const float4*)(bSrc);
    bv1 = *(const float4*)(bSrc + 4);
    As[0][aCol + 0][aRow] = av0.x; As[0][aCol + 1][aRow] = av0.y;
    As[0][aCol + 2][aRow] = av0.z; As[0][aCol + 3][aRow] = av0.w;
    As[0][aCol + 4][aRow] = av1.x; As[0][aCol + 5][aRow] = av1.y;
    As[0][aCol + 6][aRow] = av1.z; As[0][aCol + 7][aRow] = av1.w;
    *(float4*)&Bs[0][bRow][bCol]     = bv0;
    *(float4*)&Bs[0][bRow][bCol + 4] = bv1;
    __syncthreads();

    int nk = K >> 4;
    int buf = 0;
    for (int kt = 0; kt < nk; kt++) {
        if (kt + 1 < nk) {
            const float* a2 = aSrc + (size_t)(kt + 1) * 16;
            av0 = *(const float4*)(a2);
            av1 = *(const float4*)(a2 + 4);
            const float* b2 = bSrc + (size_t)(kt + 1) * 16 * N;
            bv0 = *(const float4*)(b2);
            bv1 = *(const float4*)(b2 + 4);
        }
#pragma unroll
        for (int kk = 0; kk < 16; kk++) {
            float a[8], b[8];
            *(float4*)(a)     = *(const float4*)&As[buf][kk][ty * 8];
            *(float4*)(a + 4) = *(const float4*)&As[buf][kk][ty * 8 + 4];
            *(float4*)(b)     = *(const float4*)&Bs[buf][kk][tx * 8];
            *(float4*)(b + 4) = *(const float4*)&Bs[buf][kk][tx * 8 + 4];
#pragma unroll
            for (int i = 0; i < 8; i++)
#pragma unroll
                for (int j = 0; j < 8; j++) acc[i][j] += a[i] * b[j];
        }
        if (kt + 1 < nk) {
            int w = buf ^ 1;
            As[w][aCol + 0][aRow] = av0.x; As[w][aCol + 1][aRow] = av0.y;
            As[w][aCol + 2][aRow] = av0.z; As[w][aCol + 3][aRow] = av0.w;
            As[w][aCol + 4][aRow] = av1.x; As[w][aCol + 5][aRow] = av1.y;
            As[w][aCol + 6][aRow] = av1.z; As[w][aCol + 7][aRow] = av1.w;
            *(float4*)&Bs[w][bRow][bCol]     = bv0;
            *(float4*)&Bs[w][bRow][bCol + 4] = bv1;
            __syncthreads();
            buf = w;
        }
    }

#pragma unroll
    for (int i = 0; i < 8; i++) {
        int m = m0 + ty * 8 + i;
        if (m >= Mc) break;
        int nb = n0 + tx * 8;
        float* crow = C + (size_t)m * N + nb;
#pragma unroll
        for (int j = 0; j < 8; j++) {
            float v = acc[i][j];
            if (EPI == EPI_STORE) {
                if (bias) v += bias[nb + j];
                crow[j] = v;
            } else if (EPI == EPI_SILU_MUL) {
                float g = crow[j];
                crow[j] = (g / (1.f + expf(-g))) * v;
            } else if (EPI == EPI_ADD_RES) {
                crow[j] = res[(size_t)m * N + nb + j] + v;
            } else if (EPI == EPI_FINAL) {
                size_t idx = (size_t)m * N + nb + j;
                crow[j] = res[idx] + moe[idx] + sig[m] * v;
            }
        }
    }
}

// ---------------- router: logits + softmax + top-4 + compaction + pos map ----------------
__global__ __launch_bounds__(256) void k_router(const float* __restrict__ h,
                                                const float* __restrict__ gw,
                                                float* __restrict__ logits_out,
                                                float* __restrict__ wout,
                                                int* __restrict__ cnt,
                                                int* __restrict__ rows,
                                                int* __restrict__ posOut) {
    int t = blockIdx.x, tid = threadIdx.x;
    const float* hr = h + (size_t)t * HD;
    float p[NE];
#pragma unroll
    for (int e = 0; e < NE; e++) p[e] = 0.f;
    for (int i = tid; i < HD; i += 256) {
        float hv = hr[i];
        const float* g = gw + (size_t)i * NE;
#pragma unroll
        for (int e = 0; e < NE; e++) p[e] += hv * g[e];
    }
    for (int off = 16; off; off >>= 1)
#pragma unroll
        for (int e = 0; e < NE; e++) p[e] += __shfl_down_sync(0xFFFFFFFFu, p[e], off);
    __shared__ float smr[8][NE];
    int w = tid >> 5;
    if ((tid & 31) == 0)
#pragma unroll
        for (int e = 0; e < NE; e++) smr[w][e] = p[e];
    __syncthreads();
    if (tid == 0) {
        float l[NE];
#pragma unroll
        for (int e = 0; e < NE; e++) {
            float s = 0.f;
            for (int ww = 0; ww < 8; ww++) s += smr[ww][e];
            l[e] = s;
            logits_out[(size_t)t * NE + e] = s;
        }
        float mx = l[0];
#pragma unroll
        for (int e = 1; e < NE; e++) mx = fmaxf(mx, l[e]);
        float den = 0.f, r[NE];
#pragma unroll
        for (int e = 0; e < NE; e++) { r[e] = expf(l[e] - mx); den += r[e]; }
#pragma unroll
        for (int e = 0; e < NE; e++) r[e] /= den;
        bool used[NE];
        float wrow[NE];
#pragma unroll
        for (int e = 0; e < NE; e++) { used[e] = false; wrow[e] = 0.f; }
        for (int kk = 0; kk < NTOP; kk++) {
            int bi = -1; float bv = -1.f;
            for (int e = 0; e < NE; e++)
                if (!used[e] && r[e] > bv) { bv = r[e]; bi = e; }
            used[bi] = true;
            wrow[bi] = bv;
            int pos = atomicAdd(&cnt[bi], 1);
            rows[bi * SQ + pos] = t;
            posOut[t * NE + bi] = pos;
        }
#pragma unroll
        for (int e = 0; e < NE; e++) wout[t * NE + e] = wrow[e];
    }
}

// ---------------- shared gate (sigmoid(h @ sgate)) ----------------
__global__ __launch_bounds__(256) void k_sgate(const float* __restrict__ h,
                                               const float* __restrict__ sgw,
                                               float* __restrict__ sig) {
    int t = blockIdx.x, tid = threadIdx.x;
    const float* hr = h + (size_t)t * HD;
    float s = 0.f;
    for (int i = tid; i < HD; i += 256) s += hr[i] * sgw[i];
    for (int off = 16; off; off >>= 1) s += __shfl_down_sync(0xFFFFFFFFu, s, off);
    __shared__ float red[8];
    if ((tid & 31) == 0) red[tid >> 5] = s;
    __syncthreads();
    if (tid == 0) {
        float tot = 0.f;
        for (int i = 0; i < 8; i++) tot += red[i];
        sig[t] = 1.f / (1.f + expf(-tot));
    }
}

// ---------------- deterministic MoE combine ----------------
// moe[t] = sum_e w[t,e] * edown[e][pos[t,e]]  (fixed expert order -> deterministic)
__global__ __launch_bounds__(256) void k_combine(const float* __restrict__ edown,
                                                 const float* __restrict__ w,
                                                 const int* __restrict__ pos,
                                                 float* __restrict__ moe) {
    int t = blockIdx.x, tid = threadIdx.x;
    float acc[8];
#pragma unroll
    for (int i = 0; i < 8; i++) acc[i] = 0.f;
    for (int e = 0; e < NE; e++) {
        float wv = w[t * NE + e];
        if (wv != 0.f) {
            const float* src = edown + (size_t)e * SQ * HD + (size_t)pos[t * NE + e] * HD;
#pragma unroll
            for (int i = 0; i < 8; i++) acc[i] += wv * src[tid + i * 256];
        }
    }
    float* dst = moe + (size_t)t * HD;
#pragma unroll
    for (int i = 0; i < 8; i++) dst[tid + i * 256] = acc[i];
}

// ---------------- launch ----------------
extern "C" void kernel_launch(void* const* d_in, const int* in_sizes, int n_in,
                              void* d_out, int out_size) {
    const float* x     = (const float*)d_in[0];
    const float* ln1   = (const float*)d_in[1];
    const float* ln2   = (const float*)d_in[2];
    const float* wq    = (const float*)d_in[3];
    const float* bq    = (const float*)d_in[4];
    const float* wk    = (const float*)d_in[5];
    const float* bk    = (const float*)d_in[6];
    const float* wv    = (const float*)d_in[7];
    const float* bv    = (const float*)d_in[8];
    const float* wo    = (const float*)d_in[9];
    const float* gatew = (const float*)d_in[10];
    const float* eg    = (const float*)d_in[11];
    const float* eu    = (const float*)d_in[12];
    const float* ed    = (const float*)d_in[13];
    const float* sgw   = (const float*)d_in[14];
    const float* suw   = (const float*)d_in[15];
    const float* sdw   = (const float*)d_in[16];
    const float* sgate = (const float*)d_in[17];
    float* out = (float*)d_out;

    float *h, *q, *k, *v, *attn, *x1, *moe, *sh, *eup, *edown, *w, *sig;
    int *rows, *pos, *cnt;
    cudaGetSymbolAddress((void**)&h, g_h);
    cudaGetSymbolAddress((void**)&q, g_q);
    cudaGetSymbolAddress((void**)&k, g_k);
    cudaGetSymbolAddress((void**)&v, g_v);
    cudaGetSymbolAddress((void**)&attn, g_attn);
    cudaGetSymbolAddress((void**)&x1, g_x1);
    cudaGetSymbolAddress((void**)&moe, g_moe);
    cudaGetSymbolAddress((void**)&sh, g_sh);
    cudaGetSymbolAddress((void**)&eup, g_eup);
    cudaGetSymbolAddress((void**)&edown, g_edown);
    cudaGetSymbolAddress((void**)&w, g_w);
    cudaGetSymbolAddress((void**)&sig, g_sig);
    cudaGetSymbolAddress((void**)&rows, g_rows);
    cudaGetSymbolAddress((void**)&pos, g_pos);
    cudaGetSymbolAddress((void**)&cnt, g_cnt);

    // 0. reset expert counters (inside the graph so replays are idempotent)
    k_zero_cnt<<<1, 32>>>(cnt);

    // 1. ln1
    k_rmsnorm<<<SQ, 256>>>(x, ln1, h);

    // 2. qkv
    dim3 g16(HD / 128, SQ / 128);
    k_gemm<EPI_STORE, false, false><<<g16, 256>>>(h, wq, q, SQ, HD, HD, bq, nullptr, nullptr, nullptr, nullptr, nullptr, 0, 0, 0);
    k_gemm<EPI_STORE, false, false><<<g16, 256>>>(h, wk, k, SQ, HD, HD, bk, nullptr, nullptr, nullptr, nullptr, nullptr, 0, 0, 0);
    k_gemm<EPI_STORE, false, false><<<g16, 256>>>(h, wv, v, SQ, HD, HD, bv, nullptr, nullptr, nullptr, nullptr, nullptr, 0, 0, 0);

    // 3. rope
    k_rope<<<dim3(SQ, NHD), 64>>>(q, k);

    // 4. attention
    k_attn<<<dim3(SQ / 32, NHD), 256>>>(q, k, v, attn);

    // 5. x1 = x + attn @ wo
    k_gemm<EPI_ADD_RES, false, false><<<g16, 256>>>(attn, wo, x1, SQ, HD, HD, nullptr, x, nullptr, nullptr, nullptr, nullptr, 0, 0, 0);

    // 6. ln2
    k_rmsnorm<<<SQ, 256>>>(x1, ln2, h);

    // 7. router (+logits to output tail) and shared gate
    k_router<<<SQ, 256>>>(h, gatew, out + (size_t)SQ * HD, w, cnt, rows, pos);
    k_sgate<<<SQ, 256>>>(h, sgate, sig);

    // 8. MoE experts — fused across experts via blockIdx.z
    dim3 ge(IEX / 128, SQ / 128, NE);
    k_gemm<EPI_STORE, true, true><<<ge, 256>>>(h, eg, eup,
        SQ, IEX, HD, nullptr, nullptr, rows, cnt, nullptr, nullptr,
        0, (size_t)HD * IEX, (size_t)SQ * IEX);
    k_gemm<EPI_SILU_MUL, true, true><<<ge, 256>>>(h, eu, eup,
        SQ, IEX, HD, nullptr, nullptr, rows, cnt, nullptr, nullptr,
        0, (size_t)HD * IEX, (size_t)SQ * IEX);
    dim3 gd(HD / 128, SQ / 128, NE);
    k_gemm<EPI_STORE, false, true><<<gd, 256>>>(eup, ed, edown,
        SQ, HD, IEX, nullptr, nullptr, rows, cnt, nullptr, nullptr,
        (size_t)SQ * IEX, (size_t)IEX * HD, (size_t)SQ * HD);

    // 8b. deterministic combine (fully overwrites moe)
    k_combine<<<SQ, 256>>>(edown, w, pos, moe);

    // 9. shared expert
    dim3 gs(ISH / 128, SQ / 128);
    k_gemm<EPI_STORE, false, false><<<gs, 256>>>(h, sgw, sh, SQ, ISH, HD, nullptr, nullptr, nullptr, nullptr, nullptr, nullptr, 0, 0, 0);
    k_gemm<EPI_SILU_MUL, false, false><<<gs, 256>>>(h, suw, sh, SQ, ISH, HD, nullptr, nullptr, nullptr, nullptr, nullptr, nullptr, 0, 0, 0);

    // 10. final: out = x1 + moe + sig * (sh @ sd)
    k_gemm<EPI_FINAL, false, false><<<g16, 256>>>(sh, sdw, out, SQ, HD, ISH, nullptr, x1, nullptr, nullptr, sig, moe, 0, 0, 0);
}

// round 8
// speedup vs baseline: 2.2803x; 1.5630x over previous
#include <cuda_runtime.h>
#include <math.h>
#include <stdint.h>

// ---------------- problem constants ----------------
#define SQ 2048      // sequence
#define HD 2048      // hidden
#define NHD 16       // heads
#define DH 128       // head dim
#define NE 8         // experts
#define NTOP 4       // top-k
#define IEX 1408     // expert intermediate
#define ISH 5632     // shared intermediate

// ---------------- scratch (device globals; no allocs allowed) ----------------
__device__ float g_h[SQ * HD];
__device__ float g_q[SQ * HD];
__device__ float g_k[SQ * HD];
__device__ float g_v[SQ * HD];
__device__ float g_attn[SQ * HD];
__device__ float g_x1[SQ * HD];
__device__ float g_moe[SQ * HD];
__device__ float g_sh[SQ * ISH];
__device__ float g_eup[NE * SQ * IEX];
__device__ float g_edown[NE * SQ * HD];
__device__ float g_w[SQ * NE];
__device__ float g_sig[SQ];
__device__ int   g_rows[NE * SQ];
__device__ int   g_pos[SQ * NE];
__device__ int   g_cnt[NE];

// ---------------- init (counters only) ----------------
__global__ void k_zero_cnt(int* cnt) {
    if (threadIdx.x < NE) cnt[threadIdx.x] = 0;
}

// ---------------- RMSNorm ----------------
__global__ __launch_bounds__(256) void k_rmsnorm(const float* __restrict__ x,
                                                 const float* __restrict__ w,
                                                 float* __restrict__ out) {
    int r = blockIdx.x, tid = threadIdx.x;
    const float* xr = x + (size_t)r * HD;
    float s = 0.f;
    for (int i = tid; i < HD; i += 256) { float v = xr[i]; s += v * v; }
    for (int o = 16; o; o >>= 1) s += __shfl_down_sync(0xFFFFFFFFu, s, o);
    __shared__ float red[8];
    __shared__ float rs_sh;
    if ((tid & 31) == 0) red[tid >> 5] = s;
    __syncthreads();
    if (tid == 0) {
        float t = 0.f;
        for (int i = 0; i < 8; i++) t += red[i];
        rs_sh = rsqrtf(t / (float)HD + 1e-6f);
    }
    __syncthreads();
    float rs = rs_sh;
    float* orow = out + (size_t)r * HD;
    for (int i = tid; i < HD; i += 256) orow[i] = w[i] * xr[i] * rs;
}

// ---------------- RoPE (in-place on q and k) ----------------
__global__ void k_rope(float* __restrict__ q, float* __restrict__ k) {
    int s = blockIdx.x, h = blockIdx.y, d = threadIdx.x; // d in [0,64)
    float inv = 1.0f / powf(1.0e6f, (float)d / 64.0f);
    float ang = (float)s * inv;
    float sn, c;
    sincosf(ang, &sn, &c);
    size_t b = (size_t)s * HD + (size_t)h * DH;
    float q1 = q[b + d], q2 = q[b + d + 64];
    q[b + d]      = q1 * c - q2 * sn;
    q[b + d + 64] = q2 * c + q1 * sn;
    float k1 = k[b + d], k2 = k[b + d + 64];
    k[b + d]      = k1 * c - k2 * sn;
    k[b + d + 64] = k2 * c + k1 * sn;
}

// ---------------- flash attention (fp32, causal) ----------------
__global__ __launch_bounds__(256) void k_attn(const float* __restrict__ Q,
                                              const float* __restrict__ Km,
                                              const float* __restrict__ Vm,
                                              float* __restrict__ O) {
    __shared__ float Qs[32 * 128];
    __shared__ float KV[32 * 129];
    __shared__ float Ps[32 * 32];
    int qt = blockIdx.x, h = blockIdx.y, tid = threadIdx.x;
    int warp = tid >> 5, lane = tid & 31;
    int qs = qt * 32;
    int q0 = warp * 4;

    for (int idx = tid; idx < 32 * 32; idx += 256) {
        int r = idx >> 5, c4 = (idx & 31) * 4;
        *(float4*)&Qs[r * 128 + c4] =
            *(const float4*)&Q[(size_t)(qs + r) * HD + (size_t)h * DH + c4];
    }

    float mi[4], li[4], o[4][4];
#pragma unroll
    for (int i = 0; i < 4; i++) {
        mi[i] = -INFINITY; li[i] = 0.f;
        o[i][0] = o[i][1] = o[i][2] = o[i][3] = 0.f;
    }
    const float scale = 0.08838834764831845f;

    for (int kt = 0; kt <= qt; kt++) {
        int ks = kt * 32;
        __syncthreads();
        for (int idx = tid; idx < 32 * 32; idx += 256) {
            int r = idx >> 5, c4 = (idx & 31) * 4;
            float4 kv = *(const float4*)&Km[(size_t)(ks + r) * HD + (size_t)h * DH + c4];
            float* dst = &KV[r * 129 + c4];
            dst[0] = kv.x; dst[1] = kv.y; dst[2] = kv.z; dst[3] = kv.w;
        }
        __syncthreads();

        float s[4] = {0.f, 0.f, 0.f, 0.f};
        const float* krow = &KV[lane * 129];
        for (int d = 0; d < 128; d += 4) {
            float k0 = krow[d], k1 = krow[d + 1], k2 = krow[d + 2], k3 = krow[d + 3];
#pragma unroll
            for (int i = 0; i < 4; i++) {
                float4 qv = *(float4*)&Qs[(q0 + i) * 128 + d];
                s[i] += qv.x * k0 + qv.y * k1 + qv.z * k2 + qv.w * k3;
            }
        }
#pragma unroll
        for (int i = 0; i < 4; i++) {
            s[i] *= scale;
            if (kt == qt && lane > q0 + i) s[i] = -INFINITY;
        }

#pragma unroll
        for (int i = 0; i < 4; i++) {
            float mx = s[i];
            for (int off = 16; off; off >>= 1)
                mx = fmaxf(mx, __shfl_xor_sync(0xFFFFFFFFu, mx, off));
            float mn = fmaxf(mi[i], mx);
            float alpha = expf(mi[i] - mn);
            float pv = expf(s[i] - mn);
            Ps[(q0 + i) * 32 + lane] = pv;
            float ls = pv;
            for (int off = 16; off; off >>= 1)
                ls += __shfl_xor_sync(0xFFFFFFFFu, ls, off);
            li[i] = li[i] * alpha + ls;
            mi[i] = mn;
            o[i][0] *= alpha; o[i][1] *= alpha; o[i][2] *= alpha; o[i][3] *= alpha;
        }
        __syncthreads();

        for (int idx = tid; idx < 32 * 32; idx += 256) {
            int r = idx >> 5, c4 = (idx & 31) * 4;
            *(float4*)&KV[r * 128 + c4] =
                *(const float4*)&Vm[(size_t)(ks + r) * HD + (size_t)h * DH + c4];
        }
        __syncthreads();

        for (int kk = 0; kk < 32; kk++) {
            float4 vv = *(float4*)&KV[kk * 128 + lane * 4];
#pragma unroll
            for (int i = 0; i < 4; i++) {
                float p = Ps[(q0 + i) * 32 + kk];
                o[i][0] += p * vv.x; o[i][1] += p * vv.y;
                o[i][2] += p * vv.z; o[i][3] += p * vv.w;
            }
        }
    }

#pragma unroll
    for (int i = 0; i < 4; i++) {
        float r = 1.f / li[i];
        size_t base = (size_t)(qs + q0 + i) * HD + (size_t)h * DH + lane * 4;
        O[base + 0] = o[i][0] * r; O[base + 1] = o[i][1] * r;
        O[base + 2] = o[i][2] * r; O[base + 3] = o[i][3] * r;
    }
}

// ---------------- tf32 tensor-core GEMM with epilogues ----------------
// C = A(MxK) @ B(KxN), row-major. CTA 128x128, BK=16, double-buffered.
// 8 warps (2x4); warp tile 64x32 via mma.sync.m16n8k8.tf32 (fp32 accum).
enum { EPI_STORE = 0, EPI_SILU_MUL = 1, EPI_ADD_RES = 2, EPI_FINAL = 3 };

#define A_STRIDE 20    // 128 rows x 16 cols padded -> conflict-free frag reads
#define B_STRIDE 136   // 16 rows x 128 cols padded -> conflict-free frag reads

__device__ __forceinline__ uint32_t f2tf(float f) {
    uint32_t u;
    asm("cvt.rna.tf32.f32 %0, %1;" : "=r"(u) : "f"(f));
    return u;
}

__device__ __forceinline__ void mma_tf32(float* c, const uint32_t* a, const uint32_t* b) {
    asm volatile(
        "mma.sync.aligned.m16n8k8.row.col.f32.tf32.tf32.f32 "
        "{%0,%1,%2,%3}, {%4,%5,%6,%7}, {%8,%9}, {%0,%1,%2,%3};"
        : "+f"(c[0]), "+f"(c[1]), "+f"(c[2]), "+f"(c[3])
        : "r"(a[0]), "r"(a[1]), "r"(a[2]), "r"(a[3]), "r"(b[0]), "r"(b[1]));
}

template <int EPI, bool GATHER, bool FUSEZ>
__global__ __launch_bounds__(256) void k_gemm(
    const float* __restrict__ A, const float* __restrict__ B, float* __restrict__ C,
    int M, int N, int K,
    const float* __restrict__ bias,
    const float* __restrict__ res,
    const int* __restrict__ rowIdx, const int* __restrict__ rowCnt,
    const float* __restrict__ sig, const float* __restrict__ moe,
    size_t zsA, size_t zsB, size_t zsC) {
    if (FUSEZ) {
        int z = blockIdx.z;
        A += (size_t)z * zsA; B += (size_t)z * zsB; C += (size_t)z * zsC;
        rowIdx += z * SQ; rowCnt += z;
    }
    int Mc = rowCnt ? *rowCnt : M;
    int m0 = blockIdx.y * 128;
    if (m0 >= Mc) return;
    int n0 = blockIdx.x * 128;

    __shared__ uint32_t As[2][128 * A_STRIDE];   // 20 KB
    __shared__ uint32_t Bs[2][16 * B_STRIDE];    // 17 KB

    int tid = threadIdx.x;
    int warp = tid >> 5, lane = tid & 31;
    int wm = warp >> 2, wn = warp & 3;          // 2 x 4 warp grid
    int g = lane >> 2, t = lane & 3;
    int wRow = wm * 64, wCol = wn * 32;

    // loaders
    int aRow = tid >> 1, aCol = (tid & 1) * 8;  // 128 rows x 16 cols, 2 float4/thr
    int mA = m0 + aRow; if (mA > Mc - 1) mA = Mc - 1;
    const float* aSrc = A + (size_t)(GATHER ? rowIdx[mA] : mA) * K + aCol;
    int bRow = tid >> 4, bCol = (tid & 15) * 8; // 16 rows x 128 cols, 2 float4/thr
    const float* bSrc = B + (size_t)bRow * N + n0 + bCol;

    float acc[4][4][4];
#pragma unroll
    for (int i = 0; i < 4; i++)
#pragma unroll
        for (int j = 0; j < 4; j++)
#pragma unroll
            for (int q = 0; q < 4; q++) acc[i][j][q] = 0.f;

    // prologue: tile 0
    {
        float4 a0 = *(const float4*)(aSrc);
        float4 a1 = *(const float4*)(aSrc + 4);
        float4 b0 = *(const float4*)(bSrc);
        float4 b1 = *(const float4*)(bSrc + 4);
        uint32_t* ad = &As[0][aRow * A_STRIDE + aCol];
        ad[0] = f2tf(a0.x); ad[1] = f2tf(a0.y); ad[2] = f2tf(a0.z); ad[3] = f2tf(a0.w);
        ad[4] = f2tf(a1.x); ad[5] = f2tf(a1.y); ad[6] = f2tf(a1.z); ad[7] = f2tf(a1.w);
        uint32_t* bd = &Bs[0][bRow * B_STRIDE + bCol];
        bd[0] = f2tf(b0.x); bd[1] = f2tf(b0.y); bd[2] = f2tf(b0.z); bd[3] = f2tf(b0.w);
        bd[4] = f2tf(b1.x); bd[5] = f2tf(b1.y); bd[6] = f2tf(b1.z); bd[7] = f2tf(b1.w);
    }
    __syncthreads();

    int nk = K >> 4;
    int buf = 0;
    for (int kt = 0; kt < nk; kt++) {
        float4 a0, a1, b0, b1;
        if (kt + 1 < nk) {
            const float* ap = aSrc + (size_t)(kt + 1) * 16;
            a0 = *(const float4*)(ap);
            a1 = *(const float4*)(ap + 4);
            const float* bp = bSrc + (size_t)(kt + 1) * 16 * N;
            b0 = *(const float4*)(bp);
            b1 = *(const float4*)(bp + 4);
        }
        const uint32_t* Ab = As[buf];
        const uint32_t* Bb = Bs[buf];
#pragma unroll
        for (int ks = 0; ks < 16; ks += 8) {
            uint32_t af[4][4], bf[4][2];
#pragma unroll
            for (int mt = 0; mt < 4; mt++) {
                int r = wRow + mt * 16 + g;
                af[mt][0] = Ab[r * A_STRIDE + ks + t];
                af[mt][1] = Ab[(r + 8) * A_STRIDE + ks + t];
                af[mt][2] = Ab[r * A_STRIDE + ks + t + 4];
                af[mt][3] = Ab[(r + 8) * A_STRIDE + ks + t + 4];
            }
#pragma unroll
            for (int nt = 0; nt < 4; nt++) {
                int c = wCol + nt * 8 + g;
                bf[nt][0] = Bb[(ks + t) * B_STRIDE + c];
                bf[nt][1] = Bb[(ks + t + 4) * B_STRIDE + c];
            }
#pragma unroll
            for (int mt = 0; mt < 4; mt++)
#pragma unroll
                for (int nt = 0; nt < 4; nt++)
                    mma_tf32(acc[mt][nt], af[mt], bf[nt]);
        }
        if (kt + 1 < nk) {
            int w = buf ^ 1;
            uint32_t* ad = &As[w][aRow * A_STRIDE + aCol];
            ad[0] = f2tf(a0.x); ad[1] = f2tf(a0.y); ad[2] = f2tf(a0.z); ad[3] = f2tf(a0.w);
            ad[4] = f2tf(a1.x); ad[5] = f2tf(a1.y); ad[6] = f2tf(a1.z); ad[7] = f2tf(a1.w);
            uint32_t* bd = &Bs[w][bRow * B_STRIDE + bCol];
            bd[0] = f2tf(b0.x); bd[1] = f2tf(b0.y); bd[2] = f2tf(b0.z); bd[3] = f2tf(b0.w);
            bd[4] = f2tf(b1.x); bd[5] = f2tf(b1.y); bd[6] = f2tf(b1.z); bd[7] = f2tf(b1.w);
            __syncthreads();
            buf = w;
        }
    }

    // epilogue: lane holds rows (base+g, base+g+8), cols (cbase+2t, +1)
#pragma unroll
    for (int mt = 0; mt < 4; mt++) {
#pragma unroll
        for (int half = 0; half < 2; half++) {
            int m = m0 + wRow + mt * 16 + g + half * 8;
            if (m >= Mc) continue;
#pragma unroll
            for (int nt = 0; nt < 4; nt++) {
                int c = n0 + wCol + nt * 8 + 2 * t;
                float v0 = acc[mt][nt][half * 2 + 0];
                float v1 = acc[mt][nt][half * 2 + 1];
                float* crow = C + (size_t)m * N + c;
                if (EPI == EPI_STORE) {
                    if (bias) { v0 += bias[c]; v1 += bias[c + 1]; }
                    crow[0] = v0; crow[1] = v1;
                } else if (EPI == EPI_SILU_MUL) {
                    float g0 = crow[0], g1 = crow[1];
                    crow[0] = (g0 / (1.f + expf(-g0))) * v0;
                    crow[1] = (g1 / (1.f + expf(-g1))) * v1;
                } else if (EPI == EPI_ADD_RES) {
                    const float* rrow = res + (size_t)m * N + c;
                    crow[0] = rrow[0] + v0; crow[1] = rrow[1] + v1;
                } else if (EPI == EPI_FINAL) {
                    size_t idx = (size_t)m * N + c;
                    float sg = sig[m];
                    crow[0] = res[idx] + moe[idx] + sg * v0;
                    crow[1] = res[idx + 1] + moe[idx + 1] + sg * v1;
                }
            }
        }
    }
}

// ---------------- router: logits + softmax + top-4 + compaction + pos map ----------------
__global__ __launch_bounds__(256) void k_router(const float* __restrict__ h,
                                                const float* __restrict__ gw,
                                                float* __restrict__ logits_out,
                                                float* __restrict__ wout,
                                                int* __restrict__ cnt,
                                                int* __restrict__ rows,
                                                int* __restrict__ posOut) {
    int t = blockIdx.x, tid = threadIdx.x;
    const float* hr = h + (size_t)t * HD;
    float p[NE];
#pragma unroll
    for (int e = 0; e < NE; e++) p[e] = 0.f;
    for (int i = tid; i < HD; i += 256) {
        float hv = hr[i];
        const float* g = gw + (size_t)i * NE;
#pragma unroll
        for (int e = 0; e < NE; e++) p[e] += hv * g[e];
    }
    for (int off = 16; off; off >>= 1)
#pragma unroll
        for (int e = 0; e < NE; e++) p[e] += __shfl_down_sync(0xFFFFFFFFu, p[e], off);
    __shared__ float smr[8][NE];
    int w = tid >> 5;
    if ((tid & 31) == 0)
#pragma unroll
        for (int e = 0; e < NE; e++) smr[w][e] = p[e];
    __syncthreads();
    if (tid == 0) {
        float l[NE];
#pragma unroll
        for (int e = 0; e < NE; e++) {
            float s = 0.f;
            for (int ww = 0; ww < 8; ww++) s += smr[ww][e];
            l[e] = s;
            logits_out[(size_t)t * NE + e] = s;
        }
        float mx = l[0];
#pragma unroll
        for (int e = 1; e < NE; e++) mx = fmaxf(mx, l[e]);
        float den = 0.f, r[NE];
#pragma unroll
        for (int e = 0; e < NE; e++) { r[e] = expf(l[e] - mx); den += r[e]; }
#pragma unroll
        for (int e = 0; e < NE; e++) r[e] /= den;
        bool used[NE];
        float wrow[NE];
#pragma unroll
        for (int e = 0; e < NE; e++) { used[e] = false; wrow[e] = 0.f; }
        for (int kk = 0; kk < NTOP; kk++) {
            int bi = -1; float bv = -1.f;
            for (int e = 0; e < NE; e++)
                if (!used[e] && r[e] > bv) { bv = r[e]; bi = e; }
            used[bi] = true;
            wrow[bi] = bv;
            int pos = atomicAdd(&cnt[bi], 1);
            rows[bi * SQ + pos] = t;
            posOut[t * NE + bi] = pos;
        }
#pragma unroll
        for (int e = 0; e < NE; e++) wout[t * NE + e] = wrow[e];
    }
}

// ---------------- shared gate (sigmoid(h @ sgate)) ----------------
__global__ __launch_bounds__(256) void k_sgate(const float* __restrict__ h,
                                               const float* __restrict__ sgw,
                                               float* __restrict__ sig) {
    int t = blockIdx.x, tid = threadIdx.x;
    const float* hr = h + (size_t)t * HD;
    float s = 0.f;
    for (int i = tid; i < HD; i += 256) s += hr[i] * sgw[i];
    for (int off = 16; off; off >>= 1) s += __shfl_down_sync(0xFFFFFFFFu, s, off);
    __shared__ float red[8];
    if ((tid & 31) == 0) red[tid >> 5] = s;
    __syncthreads();
    if (tid == 0) {
        float tot = 0.f;
        for (int i = 0; i < 8; i++) tot += red[i];
        sig[t] = 1.f / (1.f + expf(-tot));
    }
}

// ---------------- deterministic MoE combine ----------------
__global__ __launch_bounds__(256) void k_combine(const float* __restrict__ edown,
                                                 const float* __restrict__ w,
                                                 const int* __restrict__ pos,
                                                 float* __restrict__ moe) {
    int t = blockIdx.x, tid = threadIdx.x;
    float acc[8];
#pragma unroll
    for (int i = 0; i < 8; i++) acc[i] = 0.f;
    for (int e = 0; e < NE; e++) {
        float wv = w[t * NE + e];
        if (wv != 0.f) {
            const float* src = edown + (size_t)e * SQ * HD + (size_t)pos[t * NE + e] * HD;
#pragma unroll
            for (int i = 0; i < 8; i++) acc[i] += wv * src[tid + i * 256];
        }
    }
    float* dst = moe + (size_t)t * HD;
#pragma unroll
    for (int i = 0; i < 8; i++) dst[tid + i * 256] = acc[i];
}

// ---------------- launch ----------------
extern "C" void kernel_launch(void* const* d_in, const int* in_sizes, int n_in,
                              void* d_out, int out_size) {
    const float* x     = (const float*)d_in[0];
    const float* ln1   = (const float*)d_in[1];
    const float* ln2   = (const float*)d_in[2];
    const float* wq    = (const float*)d_in[3];
    const float* bq    = (const float*)d_in[4];
    const float* wk    = (const float*)d_in[5];
    const float* bk    = (const float*)d_in[6];
    const float* wv    = (const float*)d_in[7];
    const float* bv    = (const float*)d_in[8];
    const float* wo    = (const float*)d_in[9];
    const float* gatew = (const float*)d_in[10];
    const float* eg    = (const float*)d_in[11];
    const float* eu    = (const float*)d_in[12];
    const float* ed    = (const float*)d_in[13];
    const float* sgw   = (const float*)d_in[14];
    const float* suw   = (const float*)d_in[15];
    const float* sdw   = (const float*)d_in[16];
    const float* sgate = (const float*)d_in[17];
    float* out = (float*)d_out;

    float *h, *q, *k, *v, *attn, *x1, *moe, *sh, *eup, *edown, *w, *sig;
    int *rows, *pos, *cnt;
    cudaGetSymbolAddress((void**)&h, g_h);
    cudaGetSymbolAddress((void**)&q, g_q);
    cudaGetSymbolAddress((void**)&k, g_k);
    cudaGetSymbolAddress((void**)&v, g_v);
    cudaGetSymbolAddress((void**)&attn, g_attn);
    cudaGetSymbolAddress((void**)&x1, g_x1);
    cudaGetSymbolAddress((void**)&moe, g_moe);
    cudaGetSymbolAddress((void**)&sh, g_sh);
    cudaGetSymbolAddress((void**)&eup, g_eup);
    cudaGetSymbolAddress((void**)&edown, g_edown);
    cudaGetSymbolAddress((void**)&w, g_w);
    cudaGetSymbolAddress((void**)&sig, g_sig);
    cudaGetSymbolAddress((void**)&rows, g_rows);
    cudaGetSymbolAddress((void**)&pos, g_pos);
    cudaGetSymbolAddress((void**)&cnt, g_cnt);

    // 0. reset expert counters
    k_zero_cnt<<<1, 32>>>(cnt);

    // 1. ln1
    k_rmsnorm<<<SQ, 256>>>(x, ln1, h);

    // 2. qkv (tf32 tensor GEMM)
    dim3 g16(HD / 128, SQ / 128);
    k_gemm<EPI_STORE, false, false><<<g16, 256>>>(h, wq, q, SQ, HD, HD, bq, nullptr, nullptr, nullptr, nullptr, nullptr, 0, 0, 0);
    k_gemm<EPI_STORE, false, false><<<g16, 256>>>(h, wk, k, SQ, HD, HD, bk, nullptr, nullptr, nullptr, nullptr, nullptr, 0, 0, 0);
    k_gemm<EPI_STORE, false, false><<<g16, 256>>>(h, wv, v, SQ, HD, HD, bv, nullptr, nullptr, nullptr, nullptr, nullptr, 0, 0, 0);

    // 3. rope
    k_rope<<<dim3(SQ, NHD), 64>>>(q, k);

    // 4. attention
    k_attn<<<dim3(SQ / 32, NHD), 256>>>(q, k, v, attn);

    // 5. x1 = x + attn @ wo
    k_gemm<EPI_ADD_RES, false, false><<<g16, 256>>>(attn, wo, x1, SQ, HD, HD, nullptr, x, nullptr, nullptr, nullptr, nullptr, 0, 0, 0);

    // 6. ln2
    k_rmsnorm<<<SQ, 256>>>(x1, ln2, h);

    // 7. router (fp32, exact) and shared gate
    k_router<<<SQ, 256>>>(h, gatew, out + (size_t)SQ * HD, w, cnt, rows, pos);
    k_sgate<<<SQ, 256>>>(h, sgate, sig);

    // 8. MoE experts — fused across experts via blockIdx.z
    dim3 ge(IEX / 128, SQ / 128, NE);
    k_gemm<EPI_STORE, true, true><<<ge, 256>>>(h, eg, eup,
        SQ, IEX, HD, nullptr, nullptr, rows, cnt, nullptr, nullptr,
        0, (size_t)HD * IEX, (size_t)SQ * IEX);
    k_gemm<EPI_SILU_MUL, true, true><<<ge, 256>>>(h, eu, eup,
        SQ, IEX, HD, nullptr, nullptr, rows, cnt, nullptr, nullptr,
        0, (size_t)HD * IEX, (size_t)SQ * IEX);
    dim3 gd(HD / 128, SQ / 128, NE);
    k_gemm<EPI_STORE, false, true><<<gd, 256>>>(eup, ed, edown,
        SQ, HD, IEX, nullptr, nullptr, rows, cnt, nullptr, nullptr,
        (size_t)SQ * IEX, (size_t)IEX * HD, (size_t)SQ * HD);

    // 8b. deterministic combine
    k_combine<<<SQ, 256>>>(edown, w, pos, moe);

    // 9. shared expert
    dim3 gs(ISH / 128, SQ / 128);
    k_gemm<EPI_STORE, false, false><<<gs, 256>>>(h, sgw, sh, SQ, ISH, HD, nullptr, nullptr, nullptr, nullptr, nullptr, nullptr, 0, 0, 0);
    k_gemm<EPI_SILU_MUL, false, false><<<gs, 256>>>(h, suw, sh, SQ, ISH, HD, nullptr, nullptr, nullptr, nullptr, nullptr, nullptr, 0, 0, 0);

    // 10. final: out = x1 + moe + sig * (sh @ sd)
    k_gemm<EPI_FINAL, false, false><<<g16, 256>>>(sh, sdw, out, SQ, HD, ISH, nullptr, x1, nullptr, nullptr, sig, moe, 0, 0, 0);
}

// round 10
// speedup vs baseline: 2.5561x; 1.1210x over previous
#include <cuda_runtime.h>
#include <math.h>
#include <stdint.h>

// ---------------- problem constants ----------------
#define SQ 2048
#define HD 2048
#define NHD 16
#define DH 128
#define NE 8
#define NTOP 4
#define IEX 1408
#define ISH 5632

// ---------------- scratch ----------------
__device__ float g_h[SQ * HD];
__device__ float g_q[SQ * HD];
__device__ float g_k[SQ * HD];
__device__ float g_v[SQ * HD];
__device__ float g_attn[SQ * HD];
__device__ float g_x1[SQ * HD];
__device__ float g_moe[SQ * HD];
__device__ float g_sh[SQ * ISH];
__device__ float g_eup[NE * SQ * IEX];
__device__ float g_edown[NE * SQ * HD];
__device__ float g_w[SQ * NE];
__device__ float g_sig[SQ];
__device__ int   g_rows[NE * SQ];
__device__ int   g_pos[SQ * NE];
__device__ int   g_cnt[NE];

__global__ void k_zero_cnt(int* cnt) {
    if (threadIdx.x < NE) cnt[threadIdx.x] = 0;
}

// ---------------- RMSNorm ----------------
__global__ __launch_bounds__(256) void k_rmsnorm(const float* __restrict__ x,
                                                 const float* __restrict__ w,
                                                 float* __restrict__ out) {
    int r = blockIdx.x, tid = threadIdx.x;
    const float* xr = x + (size_t)r * HD;
    float s = 0.f;
    for (int i = tid; i < HD; i += 256) { float v = xr[i]; s += v * v; }
    for (int o = 16; o; o >>= 1) s += __shfl_down_sync(0xFFFFFFFFu, s, o);
    __shared__ float red[8];
    __shared__ float rs_sh;
    if ((tid & 31) == 0) red[tid >> 5] = s;
    __syncthreads();
    if (tid == 0) {
        float t = 0.f;
        for (int i = 0; i < 8; i++) t += red[i];
        rs_sh = rsqrtf(t / (float)HD + 1e-6f);
    }
    __syncthreads();
    float rs = rs_sh;
    float* orow = out + (size_t)r * HD;
    for (int i = tid; i < HD; i += 256) orow[i] = w[i] * xr[i] * rs;
}

// ---------------- RoPE ----------------
__global__ void k_rope(float* __restrict__ q, float* __restrict__ k) {
    int s = blockIdx.x, h = blockIdx.y, d = threadIdx.x;
    float inv = 1.0f / powf(1.0e6f, (float)d / 64.0f);
    float ang = (float)s * inv;
    float sn, c;
    sincosf(ang, &sn, &c);
    size_t b = (size_t)s * HD + (size_t)h * DH;
    float q1 = q[b + d], q2 = q[b + d + 64];
    q[b + d]      = q1 * c - q2 * sn;
    q[b + d + 64] = q2 * c + q1 * sn;
    float k1 = k[b + d], k2 = k[b + d + 64];
    k[b + d]      = k1 * c - k2 * sn;
    k[b + d + 64] = k2 * c + k1 * sn;
}

// ---------------- tf32 mma helpers ----------------
__device__ __forceinline__ uint32_t f2tf(float f) {
    uint32_t u;
    asm("cvt.rna.tf32.f32 %0, %1;" : "=r"(u) : "f"(f));
    return u;
}
__device__ __forceinline__ void mma_tf32(float* c, const uint32_t* a, const uint32_t* b) {
    asm volatile(
        "mma.sync.aligned.m16n8k8.row.col.f32.tf32.tf32.f32 "
        "{%0,%1,%2,%3}, {%4,%5,%6,%7}, {%8,%9}, {%0,%1,%2,%3};"
        : "+f"(c[0]), "+f"(c[1]), "+f"(c[2]), "+f"(c[3])
        : "r"(a[0]), "r"(a[1]), "r"(a[2]), "r"(a[3]), "r"(b[0]), "r"(b[1]));
}

// ---------------- flash attention (tf32 tensor cores, causal) ----------------
// Br=64, Bc=64; 4 warps x 32 thr; warp owns rows [16w, 16w+16).
// Strides: A-operand arrays (Qs:132, Ps:68) ≡4 mod 32; B-operand (K:132 read
// as B[n][k] -> bank 4g+t; V:136 read as B[k][n] -> bank 8t+g): conflict-free.
#define QSTR 132
#define KSTR 132
#define VSTR 136
#define PSTR 68
#define ATTN_SMEM ((64 * QSTR + 64 * VSTR + 64 * PSTR) * 4)

__global__ __launch_bounds__(128) void k_attn_mma(const float* __restrict__ Q,
                                                  const float* __restrict__ Km,
                                                  const float* __restrict__ Vm,
                                                  float* __restrict__ O) {
    extern __shared__ float sm[];
    float* Qs  = sm;                  // 64 x QSTR (tf32)
    float* KVs = sm + 64 * QSTR;      // 64 x 136 shared K then V
    float* Ps  = KVs + 64 * VSTR;     // 64 x PSTR (tf32)

    int qt = (int)gridDim.x - 1 - (int)blockIdx.x;   // longest CTAs first
    int h = blockIdx.y;
    int tid = threadIdx.x, warp = tid >> 5, lane = tid & 31;
    int g = lane >> 2, t = lane & 3;
    int qs = qt * 64;
    int r0 = warp * 16 + g;      // local rows r0, r0+8

    // load Q tile (cvt tf32)
    for (int idx = tid; idx < 64 * 32; idx += 128) {
        int r = idx >> 5, c4 = (idx & 31) * 4;
        float4 qv = *(const float4*)&Q[(size_t)(qs + r) * HD + (size_t)h * DH + c4];
        uint32_t* d = (uint32_t*)&Qs[r * QSTR + c4];
        d[0] = f2tf(qv.x); d[1] = f2tf(qv.y); d[2] = f2tf(qv.z); d[3] = f2tf(qv.w);
    }

    float oacc[16][4];
#pragma unroll
    for (int i = 0; i < 16; i++) { oacc[i][0] = oacc[i][1] = oacc[i][2] = oacc[i][3] = 0.f; }
    float m0 = -INFINITY, m1 = -INFINITY, l0 = 0.f, l1 = 0.f;
    const float scale = 0.08838834764831845f;

    const uint32_t* Qu = (const uint32_t*)Qs;
    const uint32_t* KVu = (const uint32_t*)KVs;
    uint32_t* Pu = (uint32_t*)Ps;

    for (int kt = 0; kt <= qt; kt++) {
        int ks = kt * 64;
        __syncthreads();   // prior PV reads (and Q stores on iter 0) complete
        // K tile: [kv][d] stride KSTR
        for (int idx = tid; idx < 64 * 32; idx += 128) {
            int r = idx >> 5, c4 = (idx & 31) * 4;
            float4 kv = *(const float4*)&Km[(size_t)(ks + r) * HD + (size_t)h * DH + c4];
            uint32_t* d = (uint32_t*)&KVs[r * KSTR + c4];
            d[0] = f2tf(kv.x); d[1] = f2tf(kv.y); d[2] = f2tf(kv.z); d[3] = f2tf(kv.w);
        }
        __syncthreads();

        // S = Q K^T (m16 x n64, k=128)
        float sacc[8][4];
#pragma unroll
        for (int nt = 0; nt < 8; nt++) sacc[nt][0] = sacc[nt][1] = sacc[nt][2] = sacc[nt][3] = 0.f;
#pragma unroll
        for (int kk = 0; kk < 16; kk++) {
            uint32_t af[4];
            af[0] = Qu[r0 * QSTR + kk * 8 + t];
            af[1] = Qu[(r0 + 8) * QSTR + kk * 8 + t];
            af[2] = Qu[r0 * QSTR + kk * 8 + t + 4];
            af[3] = Qu[(r0 + 8) * QSTR + kk * 8 + t + 4];
#pragma unroll
            for (int nt = 0; nt < 8; nt++) {
                uint32_t bf[2];
                bf[0] = KVu[(nt * 8 + g) * KSTR + kk * 8 + t];
                bf[1] = KVu[(nt * 8 + g) * KSTR + kk * 8 + t + 4];
                mma_tf32(sacc[nt], af, bf);
            }
        }

        // scale + causal mask + row max
        float mx0 = -INFINITY, mx1 = -INFINITY;
#pragma unroll
        for (int nt = 0; nt < 8; nt++) {
            sacc[nt][0] *= scale; sacc[nt][1] *= scale;
            sacc[nt][2] *= scale; sacc[nt][3] *= scale;
            if (kt == qt) {
                int col = nt * 8 + 2 * t;
                if (col     > r0)     sacc[nt][0] = -INFINITY;
                if (col + 1 > r0)     sacc[nt][1] = -INFINITY;
                if (col     > r0 + 8) sacc[nt][2] = -INFINITY;
                if (col + 1 > r0 + 8) sacc[nt][3] = -INFINITY;
            }
            mx0 = fmaxf(mx0, fmaxf(sacc[nt][0], sacc[nt][1]));
            mx1 = fmaxf(mx1, fmaxf(sacc[nt][2], sacc[nt][3]));
        }
        mx0 = fmaxf(mx0, __shfl_xor_sync(0xFFFFFFFFu, mx0, 1));
        mx0 = fmaxf(mx0, __shfl_xor_sync(0xFFFFFFFFu, mx0, 2));
        mx1 = fmaxf(mx1, __shfl_xor_sync(0xFFFFFFFFu, mx1, 1));
        mx1 = fmaxf(mx1, __shfl_xor_sync(0xFFFFFFFFu, mx1, 2));

        float mn0 = fmaxf(m0, mx0), mn1 = fmaxf(m1, mx1);
        float a0 = __expf(m0 - mn0), a1 = __expf(m1 - mn1);
        float ls0 = 0.f, ls1 = 0.f;
#pragma unroll
        for (int nt = 0; nt < 8; nt++) {
            float p00 = __expf(sacc[nt][0] - mn0);
            float p01 = __expf(sacc[nt][1] - mn0);
            float p10 = __expf(sacc[nt][2] - mn1);
            float p11 = __expf(sacc[nt][3] - mn1);
            ls0 += p00 + p01;
            ls1 += p10 + p11;
            uint32_t* pd0 = &Pu[r0 * PSTR + nt * 8 + 2 * t];
            pd0[0] = f2tf(p00); pd0[1] = f2tf(p01);
            uint32_t* pd1 = &Pu[(r0 + 8) * PSTR + nt * 8 + 2 * t];
            pd1[0] = f2tf(p10); pd1[1] = f2tf(p11);
        }
        ls0 += __shfl_xor_sync(0xFFFFFFFFu, ls0, 1);
        ls0 += __shfl_xor_sync(0xFFFFFFFFu, ls0, 2);
        ls1 += __shfl_xor_sync(0xFFFFFFFFu, ls1, 1);
        ls1 += __shfl_xor_sync(0xFFFFFFFFu, ls1, 2);
        l0 = l0 * a0 + ls0;
        l1 = l1 * a1 + ls1;
        m0 = mn0; m1 = mn1;
#pragma unroll
        for (int nt = 0; nt < 16; nt++) {
            oacc[nt][0] *= a0; oacc[nt][1] *= a0;
            oacc[nt][2] *= a1; oacc[nt][3] *= a1;
        }
        __syncthreads();   // K reads done, Ps visible

        // V tile: [kv][d] stride VSTR (overwrites K)
        for (int idx = tid; idx < 64 * 32; idx += 128) {
            int r = idx >> 5, c4 = (idx & 31) * 4;
            float4 vv = *(const float4*)&Vm[(size_t)(ks + r) * HD + (size_t)h * DH + c4];
            uint32_t* d = (uint32_t*)&KVs[r * VSTR + c4];
            d[0] = f2tf(vv.x); d[1] = f2tf(vv.y); d[2] = f2tf(vv.z); d[3] = f2tf(vv.w);
        }
        __syncthreads();

        // O += P V  (m16 x n128, k=64)
#pragma unroll
        for (int kk = 0; kk < 8; kk++) {
            uint32_t af[4];
            af[0] = Pu[r0 * PSTR + kk * 8 + t];
            af[1] = Pu[(r0 + 8) * PSTR + kk * 8 + t];
            af[2] = Pu[r0 * PSTR + kk * 8 + t + 4];
            af[3] = Pu[(r0 + 8) * PSTR + kk * 8 + t + 4];
#pragma unroll
            for (int nt = 0; nt < 16; nt++) {
                uint32_t bf[2];
                bf[0] = KVu[(kk * 8 + t) * VSTR + nt * 8 + g];
                bf[1] = KVu[(kk * 8 + t + 4) * VSTR + nt * 8 + g];
                mma_tf32(oacc[nt], af, bf);
            }
        }
    }

    float inv0 = 1.f / l0, inv1 = 1.f / l1;
#pragma unroll
    for (int nt = 0; nt < 16; nt++) {
        int d = nt * 8 + 2 * t;
        size_t b0 = (size_t)(qs + r0) * HD + (size_t)h * DH + d;
        size_t b1 = (size_t)(qs + r0 + 8) * HD + (size_t)h * DH + d;
        *(float2*)&O[b0] = make_float2(oacc[nt][0] * inv0, oacc[nt][1] * inv0);
        *(float2*)&O[b1] = make_float2(oacc[nt][2] * inv1, oacc[nt][3] * inv1);
    }
}

// ---------------- tf32 tensor-core GEMM with epilogues ----------------
enum { EPI_STORE = 0, EPI_SILU_MUL = 1, EPI_ADD_RES = 2, EPI_FINAL = 3 };

#define A_STRIDE 20
#define B_STRIDE 136

template <int EPI, bool GATHER, bool FUSEZ>
__global__ __launch_bounds__(256) void k_gemm(
    const float* __restrict__ A, const float* __restrict__ B, float* __restrict__ C,
    int M, int N, int K,
    const float* __restrict__ bias,
    const float* __restrict__ res,
    const int* __restrict__ rowIdx, const int* __restrict__ rowCnt,
    const float* __restrict__ sig, const float* __restrict__ moe,
    size_t zsA, size_t zsB, size_t zsC) {
    if (FUSEZ) {
        int z = blockIdx.z;
        A += (size_t)z * zsA; B += (size_t)z * zsB; C += (size_t)z * zsC;
        rowIdx += z * SQ; rowCnt += z;
    }
    int Mc = rowCnt ? *rowCnt : M;
    int m0 = blockIdx.y * 128;
    if (m0 >= Mc) return;
    int n0 = blockIdx.x * 128;

    __shared__ uint32_t As[2][128 * A_STRIDE];
    __shared__ uint32_t Bs[2][16 * B_STRIDE];

    int tid = threadIdx.x;
    int warp = tid >> 5, lane = tid & 31;
    int wm = warp >> 2, wn = warp & 3;
    int g = lane >> 2, t = lane & 3;
    int wRow = wm * 64, wCol = wn * 32;

    int aRow = tid >> 1, aCol = (tid & 1) * 8;
    int mA = m0 + aRow; if (mA > Mc - 1) mA = Mc - 1;
    const float* aSrc = A + (size_t)(GATHER ? rowIdx[mA] : mA) * K + aCol;
    int bRow = tid >> 4, bCol = (tid & 15) * 8;
    const float* bSrc = B + (size_t)bRow * N + n0 + bCol;

    float acc[4][4][4];
#pragma unroll
    for (int i = 0; i < 4; i++)
#pragma unroll
        for (int j = 0; j < 4; j++)
#pragma unroll
            for (int q = 0; q < 4; q++) acc[i][j][q] = 0.f;

    {
        float4 a0 = *(const float4*)(aSrc);
        float4 a1 = *(const float4*)(aSrc + 4);
        float4 b0 = *(const float4*)(bSrc);
        float4 b1 = *(const float4*)(bSrc + 4);
        uint32_t* ad = &As[0][aRow * A_STRIDE + aCol];
        ad[0] = f2tf(a0.x); ad[1] = f2tf(a0.y); ad[2] = f2tf(a0.z); ad[3] = f2tf(a0.w);
        ad[4] = f2tf(a1.x); ad[5] = f2tf(a1.y); ad[6] = f2tf(a1.z); ad[7] = f2tf(a1.w);
        uint32_t* bd = &Bs[0][bRow * B_STRIDE + bCol];
        bd[0] = f2tf(b0.x); bd[1] = f2tf(b0.y); bd[2] = f2tf(b0.z); bd[3] = f2tf(b0.w);
        bd[4] = f2tf(b1.x); bd[5] = f2tf(b1.y); bd[6] = f2tf(b1.z); bd[7] = f2tf(b1.w);
    }
    __syncthreads();

    int nk = K >> 4;
    int buf = 0;
    for (int kt = 0; kt < nk; kt++) {
        float4 a0, a1, b0, b1;
        if (kt + 1 < nk) {
            const float* ap = aSrc + (size_t)(kt + 1) * 16;
            a0 = *(const float4*)(ap);
            a1 = *(const float4*)(ap + 4);
            const float* bp = bSrc + (size_t)(kt + 1) * 16 * N;
            b0 = *(const float4*)(bp);
            b1 = *(const float4*)(bp + 4);
        }
        const uint32_t* Ab = As[buf];
        const uint32_t* Bb = Bs[buf];
#pragma unroll
        for (int ks = 0; ks < 16; ks += 8) {
            uint32_t af[4][4], bf[4][2];
#pragma unroll
            for (int mt = 0; mt < 4; mt++) {
                int r = wRow + mt * 16 + g;
                af[mt][0] = Ab[r * A_STRIDE + ks + t];
                af[mt][1] = Ab[(r + 8) * A_STRIDE + ks + t];
                af[mt][2] = Ab[r * A_STRIDE + ks + t + 4];
                af[mt][3] = Ab[(r + 8) * A_STRIDE + ks + t + 4];
            }
#pragma unroll
            for (int nt = 0; nt < 4; nt++) {
                int c = wCol + nt * 8 + g;
                bf[nt][0] = Bb[(ks + t) * B_STRIDE + c];
                bf[nt][1] = Bb[(ks + t + 4) * B_STRIDE + c];
            }
#pragma unroll
            for (int mt = 0; mt < 4; mt++)
#pragma unroll
                for (int nt = 0; nt < 4; nt++)
                    mma_tf32(acc[mt][nt], af[mt], bf[nt]);
        }
        if (kt + 1 < nk) {
            int w = buf ^ 1;
            uint32_t* ad = &As[w][aRow * A_STRIDE + aCol];
            ad[0] = f2tf(a0.x); ad[1] = f2tf(a0.y); ad[2] = f2tf(a0.z); ad[3] = f2tf(a0.w);
            ad[4] = f2tf(a1.x); ad[5] = f2tf(a1.y); ad[6] = f2tf(a1.z); ad[7] = f2tf(a1.w);
            uint32_t* bd = &Bs[w][bRow * B_STRIDE + bCol];
            bd[0] = f2tf(b0.x); bd[1] = f2tf(b0.y); bd[2] = f2tf(b0.z); bd[3] = f2tf(b0.w);
            bd[4] = f2tf(b1.x); bd[5] = f2tf(b1.y); bd[6] = f2tf(b1.z); bd[7] = f2tf(b1.w);
            __syncthreads();
            buf = w;
        }
    }

#pragma unroll
    for (int mt = 0; mt < 4; mt++) {
#pragma unroll
        for (int half = 0; half < 2; half++) {
            int m = m0 + wRow + mt * 16 + g + half * 8;
            if (m >= Mc) continue;
#pragma unroll
            for (int nt = 0; nt < 4; nt++) {
                int c = n0 + wCol + nt * 8 + 2 * t;
                float v0 = acc[mt][nt][half * 2 + 0];
                float v1 = acc[mt][nt][half * 2 + 1];
                float* crow = C + (size_t)m * N + c;
                if (EPI == EPI_STORE) {
                    if (bias) { v0 += bias[c]; v1 += bias[c + 1]; }
                    crow[0] = v0; crow[1] = v1;
                } else if (EPI == EPI_SILU_MUL) {
                    float g0 = crow[0], g1 = crow[1];
                    crow[0] = (g0 / (1.f + __expf(-g0))) * v0;
                    crow[1] = (g1 / (1.f + __expf(-g1))) * v1;
                } else if (EPI == EPI_ADD_RES) {
                    const float* rrow = res + (size_t)m * N + c;
                    crow[0] = rrow[0] + v0; crow[1] = rrow[1] + v1;
                } else if (EPI == EPI_FINAL) {
                    size_t idx = (size_t)m * N + c;
                    float sg = sig[m];
                    crow[0] = res[idx] + moe[idx] + sg * v0;
                    crow[1] = res[idx + 1] + moe[idx + 1] + sg * v1;
                }
            }
        }
    }
}

// ---------------- router ----------------
__global__ __launch_bounds__(256) void k_router(const float* __restrict__ h,
                                                const float* __restrict__ gw,
                                                float* __restrict__ logits_out,
                                                float* __restrict__ wout,
                                                int* __restrict__ cnt,
                                                int* __restrict__ rows,
                                                int* __restrict__ posOut) {
    int t = blockIdx.x, tid = threadIdx.x;
    const float* hr = h + (size_t)t * HD;
    float p[NE];
#pragma unroll
    for (int e = 0; e < NE; e++) p[e] = 0.f;
    for (int i = tid; i < HD; i += 256) {
        float hv = hr[i];
        const float* g = gw + (size_t)i * NE;
#pragma unroll
        for (int e = 0; e < NE; e++) p[e] += hv * g[e];
    }
    for (int off = 16; off; off >>= 1)
#pragma unroll
        for (int e = 0; e < NE; e++) p[e] += __shfl_down_sync(0xFFFFFFFFu, p[e], off);
    __shared__ float smr[8][NE];
    int w = tid >> 5;
    if ((tid & 31) == 0)
#pragma unroll
        for (int e = 0; e < NE; e++) smr[w][e] = p[e];
    __syncthreads();
    if (tid == 0) {
        float l[NE];
#pragma unroll
        for (int e = 0; e < NE; e++) {
            float s = 0.f;
            for (int ww = 0; ww < 8; ww++) s += smr[ww][e];
            l[e] = s;
            logits_out[(size_t)t * NE + e] = s;
        }
        float mx = l[0];
#pragma unroll
        for (int e = 1; e < NE; e++) mx = fmaxf(mx, l[e]);
        float den = 0.f, r[NE];
#pragma unroll
        for (int e = 0; e < NE; e++) { r[e] = expf(l[e] - mx); den += r[e]; }
#pragma unroll
        for (int e = 0; e < NE; e++) r[e] /= den;
        bool used[NE];
        float wrow[NE];
#pragma unroll
        for (int e = 0; e < NE; e++) { used[e] = false; wrow[e] = 0.f; }
        for (int kk = 0; kk < NTOP; kk++) {
            int bi = -1; float bv = -1.f;
            for (int e = 0; e < NE; e++)
                if (!used[e] && r[e] > bv) { bv = r[e]; bi = e; }
            used[bi] = true;
            wrow[bi] = bv;
            int pos = atomicAdd(&cnt[bi], 1);
            rows[bi * SQ + pos] = t;
            posOut[t * NE + bi] = pos;
        }
#pragma unroll
        for (int e = 0; e < NE; e++) wout[t * NE + e] = wrow[e];
    }
}

// ---------------- shared gate ----------------
__global__ __launch_bounds__(256) void k_sgate(const float* __restrict__ h,
                                               const float* __restrict__ sgw,
                                               float* __restrict__ sig) {
    int t = blockIdx.x, tid = threadIdx.x;
    const float* hr = h + (size_t)t * HD;
    float s = 0.f;
    for (int i = tid; i < HD; i += 256) s += hr[i] * sgw[i];
    for (int off = 16; off; off >>= 1) s += __shfl_down_sync(0xFFFFFFFFu, s, off);
    __shared__ float red[8];
    if ((tid & 31) == 0) red[tid >> 5] = s;
    __syncthreads();
    if (tid == 0) {
        float tot = 0.f;
        for (int i = 0; i < 8; i++) tot += red[i];
        sig[t] = 1.f / (1.f + expf(-tot));
    }
}

// ---------------- deterministic MoE combine ----------------
__global__ __launch_bounds__(256) void k_combine(const float* __restrict__ edown,
                                                 const float* __restrict__ w,
                                                 const int* __restrict__ pos,
                                                 float* __restrict__ moe) {
    int t = blockIdx.x, tid = threadIdx.x;
    float acc[8];
#pragma unroll
    for (int i = 0; i < 8; i++) acc[i] = 0.f;
    for (int e = 0; e < NE; e++) {
        float wv = w[t * NE + e];
        if (wv != 0.f) {
            const float* src = edown + (size_t)e * SQ * HD + (size_t)pos[t * NE + e] * HD;
#pragma unroll
            for (int i = 0; i < 8; i++) acc[i] += wv * src[tid + i * 256];
        }
    }
    float* dst = moe + (size_t)t * HD;
#pragma unroll
    for (int i = 0; i < 8; i++) dst[tid + i * 256] = acc[i];
}

// ---------------- launch ----------------
extern "C" void kernel_launch(void* const* d_in, const int* in_sizes, int n_in,
                              void* d_out, int out_size) {
    const float* x     = (const float*)d_in[0];
    const float* ln1   = (const float*)d_in[1];
    const float* ln2   = (const float*)d_in[2];
    const float* wq    = (const float*)d_in[3];
    const float* bq    = (const float*)d_in[4];
    const float* wk    = (const float*)d_in[5];
    const float* bk    = (const float*)d_in[6];
    const float* wv    = (const float*)d_in[7];
    const float* bv    = (const float*)d_in[8];
    const float* wo    = (const float*)d_in[9];
    const float* gatew = (const float*)d_in[10];
    const float* eg    = (const float*)d_in[11];
    const float* eu    = (const float*)d_in[12];
    const float* ed    = (const float*)d_in[13];
    const float* sgw   = (const float*)d_in[14];
    const float* suw   = (const float*)d_in[15];
    const float* sdw   = (const float*)d_in[16];
    const float* sgate = (const float*)d_in[17];
    float* out = (float*)d_out;

    float *h, *q, *k, *v, *attn, *x1, *moe, *sh, *eup, *edown, *w, *sig;
    int *rows, *pos, *cnt;
    cudaGetSymbolAddress((void**)&h, g_h);
    cudaGetSymbolAddress((void**)&q, g_q);
    cudaGetSymbolAddress((void**)&k, g_k);
    cudaGetSymbolAddress((void**)&v, g_v);
    cudaGetSymbolAddress((void**)&attn, g_attn);
    cudaGetSymbolAddress((void**)&x1, g_x1);
    cudaGetSymbolAddress((void**)&moe, g_moe);
    cudaGetSymbolAddress((void**)&sh, g_sh);
    cudaGetSymbolAddress((void**)&eup, g_eup);
    cudaGetSymbolAddress((void**)&edown, g_edown);
    cudaGetSymbolAddress((void**)&w, g_w);
    cudaGetSymbolAddress((void**)&sig, g_sig);
    cudaGetSymbolAddress((void**)&rows, g_rows);
    cudaGetSymbolAddress((void**)&pos, g_pos);
    cudaGetSymbolAddress((void**)&cnt, g_cnt);

    cudaFuncSetAttribute(k_attn_mma, cudaFuncAttributeMaxDynamicSharedMemorySize, ATTN_SMEM);

    // 0. reset expert counters
    k_zero_cnt<<<1, 32>>>(cnt);

    // 1. ln1
    k_rmsnorm<<<SQ, 256>>>(x, ln1, h);

    // 2. qkv
    dim3 g16(HD / 128, SQ / 128);
    k_gemm<EPI_STORE, false, false><<<g16, 256>>>(h, wq, q, SQ, HD, HD, bq, nullptr, nullptr, nullptr, nullptr, nullptr, 0, 0, 0);
    k_gemm<EPI_STORE, false, false><<<g16, 256>>>(h, wk, k, SQ, HD, HD, bk, nullptr, nullptr, nullptr, nullptr, nullptr, 0, 0, 0);
    k_gemm<EPI_STORE, false, false><<<g16, 256>>>(h, wv, v, SQ, HD, HD, bv, nullptr, nullptr, nullptr, nullptr, nullptr, 0, 0, 0);

    // 3. rope
    k_rope<<<dim3(SQ, NHD), 64>>>(q, k);

    // 4. attention (tf32 tensor cores)
    k_attn_mma<<<dim3(SQ / 64, NHD), 128, ATTN_SMEM>>>(q, k, v, attn);

    // 5. x1 = x + attn @ wo
    k_gemm<EPI_ADD_RES, false, false><<<g16, 256>>>(attn, wo, x1, SQ, HD, HD, nullptr, x, nullptr, nullptr, nullptr, nullptr, 0, 0, 0);

    // 6. ln2
    k_rmsnorm<<<SQ, 256>>>(x1, ln2, h);

    // 7. router + shared gate
    k_router<<<SQ, 256>>>(h, gatew, out + (size_t)SQ * HD, w, cnt, rows, pos);
    k_sgate<<<SQ, 256>>>(h, sgate, sig);

    // 8. MoE experts (fused over experts via blockIdx.z)
    dim3 ge(IEX / 128, SQ / 128, NE);
    k_gemm<EPI_STORE, true, true><<<ge, 256>>>(h, eg, eup,
        SQ, IEX, HD, nullptr, nullptr, rows, cnt, nullptr, nullptr,
        0, (size_t)HD * IEX, (size_t)SQ * IEX);
    k_gemm<EPI_SILU_MUL, true, true><<<ge, 256>>>(h, eu, eup,
        SQ, IEX, HD, nullptr, nullptr, rows, cnt, nullptr, nullptr,
        0, (size_t)HD * IEX, (size_t)SQ * IEX);
    dim3 gd(HD / 128, SQ / 128, NE);
    k_gemm<EPI_STORE, false, true><<<gd, 256>>>(eup, ed, edown,
        SQ, HD, IEX, nullptr, nullptr, rows, cnt, nullptr, nullptr,
        (size_t)SQ * IEX, (size_t)IEX * HD, (size_t)SQ * HD);

    // 8b. combine
    k_combine<<<SQ, 256>>>(edown, w, pos, moe);

    // 9. shared expert
    dim3 gs(ISH / 128, SQ / 128);
    k_gemm<EPI_STORE, false, false><<<gs, 256>>>(h, sgw, sh, SQ, ISH, HD, nullptr, nullptr, nullptr, nullptr, nullptr, nullptr, 0, 0, 0);
    k_gemm<EPI_SILU_MUL, false, false><<<gs, 256>>>(h, suw, sh, SQ, ISH, HD, nullptr, nullptr, nullptr, nullptr, nullptr, nullptr, 0, 0, 0);

    // 10. final
    k_gemm<EPI_FINAL, false, false><<<g16, 256>>>(sh, sdw, out, SQ, HD, ISH, nullptr, x1, nullptr, nullptr, sig, moe, 0, 0, 0);
}

// round 13
// speedup vs baseline: 3.1015x; 1.2134x over previous
#include <cuda_runtime.h>
#include <cuda_fp16.h>
#include <math.h>
#include <stdint.h>

// ---------------- problem constants ----------------
#define SQ 2048
#define HD 2048
#define NHD 16
#define DH 128
#define NE 8
#define NTOP 4
#define IEX 1408
#define ISH 5632

// ---------------- scratch ----------------
__device__ float g_h[SQ * HD];
__device__ float g_q[SQ * HD];
__device__ float g_k[SQ * HD];
__device__ float g_v[SQ * HD];
__device__ float g_attn[SQ * HD];
__device__ float g_x1[SQ * HD];
__device__ float g_moe[SQ * HD];
__device__ float g_sh[SQ * ISH];
__device__ float g_eup[NE * SQ * IEX];
__device__ float g_edown[NE * SQ * HD];
__device__ float g_w[SQ * NE];
__device__ float g_sig[SQ];
__device__ int   g_rows[NE * SQ];
__device__ int   g_pos[SQ * NE];
__device__ int   g_cnt[NE];

__global__ void k_zero_cnt(int* cnt) {
    if (threadIdx.x < NE) cnt[threadIdx.x] = 0;
}

// ---------------- RMSNorm ----------------
__global__ __launch_bounds__(256) void k_rmsnorm(const float* __restrict__ x,
                                                 const float* __restrict__ w,
                                                 float* __restrict__ out) {
    int r = blockIdx.x, tid = threadIdx.x;
    const float* xr = x + (size_t)r * HD;
    float s = 0.f;
    for (int i = tid; i < HD; i += 256) { float v = xr[i]; s += v * v; }
    for (int o = 16; o; o >>= 1) s += __shfl_down_sync(0xFFFFFFFFu, s, o);
    __shared__ float red[8];
    __shared__ float rs_sh;
    if ((tid & 31) == 0) red[tid >> 5] = s;
    __syncthreads();
    if (tid == 0) {
        float t = 0.f;
        for (int i = 0; i < 8; i++) t += red[i];
        rs_sh = rsqrtf(t / (float)HD + 1e-6f);
    }
    __syncthreads();
    float rs = rs_sh;
    float* orow = out + (size_t)r * HD;
    for (int i = tid; i < HD; i += 256) orow[i] = w[i] * xr[i] * rs;
}

// ---------------- RoPE ----------------
__global__ void k_rope(float* __restrict__ q, float* __restrict__ k) {
    int s = blockIdx.x, h = blockIdx.y, d = threadIdx.x;
    float inv = 1.0f / powf(1.0e6f, (float)d / 64.0f);
    float ang = (float)s * inv;
    float sn, c;
    sincosf(ang, &sn, &c);
    size_t b = (size_t)s * HD + (size_t)h * DH;
    float q1 = q[b + d], q2 = q[b + d + 64];
    q[b + d]      = q1 * c - q2 * sn;
    q[b + d + 64] = q2 * c + q1 * sn;
    float k1 = k[b + d], k2 = k[b + d + 64];
    k[b + d]      = k1 * c - k2 * sn;
    k[b + d + 64] = k2 * c + k1 * sn;
}

// ---------------- tf32 mma helpers (attention) ----------------
__device__ __forceinline__ uint32_t f2tf(float f) {
    uint32_t u;
    asm("cvt.rna.tf32.f32 %0, %1;" : "=r"(u) : "f"(f));
    return u;
}
__device__ __forceinline__ void mma_tf32(float* c, const uint32_t* a, const uint32_t* b) {
    asm volatile(
        "mma.sync.aligned.m16n8k8.row.col.f32.tf32.tf32.f32 "
        "{%0,%1,%2,%3}, {%4,%5,%6,%7}, {%8,%9}, {%0,%1,%2,%3};"
        : "+f"(c[0]), "+f"(c[1]), "+f"(c[2]), "+f"(c[3])
        : "r"(a[0]), "r"(a[1]), "r"(a[2]), "r"(a[3]), "r"(b[0]), "r"(b[1]));
}

// ---------------- flash attention (tf32 tensor cores, causal) ----------------
#define QSTR 132
#define KSTR 132
#define VSTR 136
#define PSTR 68
#define ATTN_SMEM ((64 * QSTR + 64 * VSTR + 64 * PSTR) * 4)

__global__ __launch_bounds__(128) void k_attn_mma(const float* __restrict__ Q,
                                                  const float* __restrict__ Km,
                                                  const float* __restrict__ Vm,
                                                  float* __restrict__ O) {
    extern __shared__ float sm[];
    float* Qs  = sm;
    float* KVs = sm + 64 * QSTR;
    float* Ps  = KVs + 64 * VSTR;

    int qt = (int)gridDim.x - 1 - (int)blockIdx.x;
    int h = blockIdx.y;
    int tid = threadIdx.x, warp = tid >> 5, lane = tid & 31;
    int g = lane >> 2, t = lane & 3;
    int qs = qt * 64;
    int r0 = warp * 16 + g;

    for (int idx = tid; idx < 64 * 32; idx += 128) {
        int r = idx >> 5, c4 = (idx & 31) * 4;
        float4 qv = *(const float4*)&Q[(size_t)(qs + r) * HD + (size_t)h * DH + c4];
        uint32_t* d = (uint32_t*)&Qs[r * QSTR + c4];
        d[0] = f2tf(qv.x); d[1] = f2tf(qv.y); d[2] = f2tf(qv.z); d[3] = f2tf(qv.w);
    }

    float oacc[16][4];
#pragma unroll
    for (int i = 0; i < 16; i++) { oacc[i][0] = oacc[i][1] = oacc[i][2] = oacc[i][3] = 0.f; }
    float m0 = -INFINITY, m1 = -INFINITY, l0 = 0.f, l1 = 0.f;
    const float scale = 0.08838834764831845f;

    const uint32_t* Qu = (const uint32_t*)Qs;
    const uint32_t* KVu = (const uint32_t*)KVs;
    uint32_t* Pu = (uint32_t*)Ps;

    for (int kt = 0; kt <= qt; kt++) {
        int ks = kt * 64;
        __syncthreads();
        for (int idx = tid; idx < 64 * 32; idx += 128) {
            int r = idx >> 5, c4 = (idx & 31) * 4;
            float4 kv = *(const float4*)&Km[(size_t)(ks + r) * HD + (size_t)h * DH + c4];
            uint32_t* d = (uint32_t*)&KVs[r * KSTR + c4];
            d[0] = f2tf(kv.x); d[1] = f2tf(kv.y); d[2] = f2tf(kv.z); d[3] = f2tf(kv.w);
        }
        __syncthreads();

        float sacc[8][4];
#pragma unroll
        for (int nt = 0; nt < 8; nt++) sacc[nt][0] = sacc[nt][1] = sacc[nt][2] = sacc[nt][3] = 0.f;
#pragma unroll
        for (int kk = 0; kk < 16; kk++) {
            uint32_t af[4];
            af[0] = Qu[r0 * QSTR + kk * 8 + t];
            af[1] = Qu[(r0 + 8) * QSTR + kk * 8 + t];
            af[2] = Qu[r0 * QSTR + kk * 8 + t + 4];
            af[3] = Qu[(r0 + 8) * QSTR + kk * 8 + t + 4];
#pragma unroll
            for (int nt = 0; nt < 8; nt++) {
                uint32_t bf[2];
                bf[0] = KVu[(nt * 8 + g) * KSTR + kk * 8 + t];
                bf[1] = KVu[(nt * 8 + g) * KSTR + kk * 8 + t + 4];
                mma_tf32(sacc[nt], af, bf);
            }
        }

        float mx0 = -INFINITY, mx1 = -INFINITY;
#pragma unroll
        for (int nt = 0; nt < 8; nt++) {
            sacc[nt][0] *= scale; sacc[nt][1] *= scale;
            sacc[nt][2] *= scale; sacc[nt][3] *= scale;
            if (kt == qt) {
                int col = nt * 8 + 2 * t;
                if (col     > r0)     sacc[nt][0] = -INFINITY;
                if (col + 1 > r0)     sacc[nt][1] = -INFINITY;
                if (col     > r0 + 8) sacc[nt][2] = -INFINITY;
                if (col + 1 > r0 + 8) sacc[nt][3] = -INFINITY;
            }
            mx0 = fmaxf(mx0, fmaxf(sacc[nt][0], sacc[nt][1]));
            mx1 = fmaxf(mx1, fmaxf(sacc[nt][2], sacc[nt][3]));
        }
        mx0 = fmaxf(mx0, __shfl_xor_sync(0xFFFFFFFFu, mx0, 1));
        mx0 = fmaxf(mx0, __shfl_xor_sync(0xFFFFFFFFu, mx0, 2));
        mx1 = fmaxf(mx1, __shfl_xor_sync(0xFFFFFFFFu, mx1, 1));
        mx1 = fmaxf(mx1, __shfl_xor_sync(0xFFFFFFFFu, mx1, 2));

        float mn0 = fmaxf(m0, mx0), mn1 = fmaxf(m1, mx1);
        float a0 = __expf(m0 - mn0), a1 = __expf(m1 - mn1);
        float ls0 = 0.f, ls1 = 0.f;
#pragma unroll
        for (int nt = 0; nt < 8; nt++) {
            float p00 = __expf(sacc[nt][0] - mn0);
            float p01 = __expf(sacc[nt][1] - mn0);
            float p10 = __expf(sacc[nt][2] - mn1);
            float p11 = __expf(sacc[nt][3] - mn1);
            ls0 += p00 + p01;
            ls1 += p10 + p11;
            uint32_t* pd0 = &Pu[r0 * PSTR + nt * 8 + 2 * t];
            pd0[0] = f2tf(p00); pd0[1] = f2tf(p01);
            uint32_t* pd1 = &Pu[(r0 + 8) * PSTR + nt * 8 + 2 * t];
            pd1[0] = f2tf(p10); pd1[1] = f2tf(p11);
        }
        ls0 += __shfl_xor_sync(0xFFFFFFFFu, ls0, 1);
        ls0 += __shfl_xor_sync(0xFFFFFFFFu, ls0, 2);
        ls1 += __shfl_xor_sync(0xFFFFFFFFu, ls1, 1);
        ls1 += __shfl_xor_sync(0xFFFFFFFFu, ls1, 2);
        l0 = l0 * a0 + ls0;
        l1 = l1 * a1 + ls1;
        m0 = mn0; m1 = mn1;
#pragma unroll
        for (int nt = 0; nt < 16; nt++) {
            oacc[nt][0] *= a0; oacc[nt][1] *= a0;
            oacc[nt][2] *= a1; oacc[nt][3] *= a1;
        }
        __syncthreads();

        for (int idx = tid; idx < 64 * 32; idx += 128) {
            int r = idx >> 5, c4 = (idx & 31) * 4;
            float4 vv = *(const float4*)&Vm[(size_t)(ks + r) * HD + (size_t)h * DH + c4];
            uint32_t* d = (uint32_t*)&KVs[r * VSTR + c4];
            d[0] = f2tf(vv.x); d[1] = f2tf(vv.y); d[2] = f2tf(vv.z); d[3] = f2tf(vv.w);
        }
        __syncthreads();

#pragma unroll
        for (int kk = 0; kk < 8; kk++) {
            uint32_t af[4];
            af[0] = Pu[r0 * PSTR + kk * 8 + t];
            af[1] = Pu[(r0 + 8) * PSTR + kk * 8 + t];
            af[2] = Pu[r0 * PSTR + kk * 8 + t + 4];
            af[3] = Pu[(r0 + 8) * PSTR + kk * 8 + t + 4];
#pragma unroll
            for (int nt = 0; nt < 16; nt++) {
                uint32_t bf[2];
                bf[0] = KVu[(kk * 8 + t) * VSTR + nt * 8 + g];
                bf[1] = KVu[(kk * 8 + t + 4) * VSTR + nt * 8 + g];
                mma_tf32(oacc[nt], af, bf);
            }
        }
    }

    float inv0 = 1.f / l0, inv1 = 1.f / l1;
#pragma unroll
    for (int nt = 0; nt < 16; nt++) {
        int d = nt * 8 + 2 * t;
        size_t b0 = (size_t)(qs + r0) * HD + (size_t)h * DH + d;
        size_t b1 = (size_t)(qs + r0 + 8) * HD + (size_t)h * DH + d;
        *(float2*)&O[b0] = make_float2(oacc[nt][0] * inv0, oacc[nt][1] * inv0);
        *(float2*)&O[b1] = make_float2(oacc[nt][2] * inv1, oacc[nt][3] * inv1);
    }
}

// ================= fp16 HMMA GEMM (ldmatrix + m16n8k16) =================
// C = A(MxK) @ B(KxN), row-major fp32 gmem; fp16 smem; fp32 accum.
// CTA 128x128, BK=32, double-buffered; 8 warps (2x4), warp tile 64x32.
// Strides in halves: A=40 (80B rows: 80r mod 128 all-distinct -> LDSM
// conflict-free), B=136 (272B rows: 16r mod 128 all-distinct).
enum { EPI_STORE = 0, EPI_SILU_MUL = 1, EPI_ADD_RES = 2, EPI_FINAL = 3 };

#define A_STR 40
#define B_STR 136

__device__ __forceinline__ uint32_t smem_u32(const void* p) {
    uint32_t a;
    asm("{ .reg .u64 t; cvta.to.shared.u64 t, %1; cvt.u32.u64 %0, t; }" : "=r"(a) : "l"(p));
    return a;
}
__device__ __forceinline__ uint32_t h2u(float a, float b) {
    __half2 h = __floats2half2_rn(a, b);
    return *(uint32_t*)&h;
}
__device__ __forceinline__ void ldsm4(uint32_t* r, uint32_t addr) {
    asm volatile("ldmatrix.sync.aligned.m8n8.x4.shared.b16 {%0,%1,%2,%3}, [%4];"
                 : "=r"(r[0]), "=r"(r[1]), "=r"(r[2]), "=r"(r[3]) : "r"(addr));
}
__device__ __forceinline__ void ldsm4t(uint32_t* r, uint32_t addr) {
    asm volatile("ldmatrix.sync.aligned.m8n8.x4.trans.shared.b16 {%0,%1,%2,%3}, [%4];"
                 : "=r"(r[0]), "=r"(r[1]), "=r"(r[2]), "=r"(r[3]) : "r"(addr));
}
__device__ __forceinline__ void mma_f16(float* c, const uint32_t* a, const uint32_t* b) {
    asm volatile(
        "mma.sync.aligned.m16n8k16.row.col.f32.f16.f16.f32 "
        "{%0,%1,%2,%3}, {%4,%5,%6,%7}, {%8,%9}, {%0,%1,%2,%3};"
        : "+f"(c[0]), "+f"(c[1]), "+f"(c[2]), "+f"(c[3])
        : "r"(a[0]), "r"(a[1]), "r"(a[2]), "r"(a[3]), "r"(b[0]), "r"(b[1]));
}

template <int EPI, bool GATHER, bool FUSEZ>
__global__ __launch_bounds__(256) void k_gemm(
    const float* __restrict__ A, const float* __restrict__ B, float* __restrict__ C,
    int M, int N, int K,
    const float* __restrict__ bias,
    const float* __restrict__ res,
    const int* __restrict__ rowIdx, const int* __restrict__ rowCnt,
    const float* __restrict__ sig, const float* __restrict__ moe,
    size_t zsA, size_t zsB, size_t zsC) {
    if (FUSEZ) {
        int z = blockIdx.z;
        A += (size_t)z * zsA; B += (size_t)z * zsB; C += (size_t)z * zsC;
        rowIdx += z * SQ; rowCnt += z;
    }
    int Mc = rowCnt ? *rowCnt : M;
    int m0 = blockIdx.y * 128;
    if (m0 >= Mc) return;
    int n0 = blockIdx.x * 128;

    __shared__ __half As[2][128 * A_STR];   // 20 KB
    __shared__ __half Bs[2][32 * B_STR];    // 17 KB

    int tid = threadIdx.x;
    int warp = tid >> 5, lane = tid & 31;
    int wm = warp >> 2, wn = warp & 3;
    int wRow = wm * 64, wCol = wn * 32;

    // loaders: A 128 rows x 32 halves (thread: row=tid>>1, 16 halves)
    int aRow = tid >> 1, aHalf = (tid & 1) * 16;
    int mA = m0 + aRow; if (mA > Mc - 1) mA = Mc - 1;
    const float* aSrc = A + (size_t)(GATHER ? rowIdx[mA] : mA) * K + aHalf;
    // B 32 k-rows x 128 halves (thread: krow=tid>>3, 16 halves in n)
    int bRow = tid >> 3, bHalf = (tid & 7) * 16;
    const float* bSrc = B + (size_t)bRow * N + n0 + bHalf;

    float acc[4][4][4];
#pragma unroll
    for (int i = 0; i < 4; i++)
#pragma unroll
        for (int j = 0; j < 4; j++)
#pragma unroll
            for (int q = 0; q < 4; q++) acc[i][j][q] = 0.f;

    // prologue: tile 0 straight to smem
    {
        uint32_t pa[8], pb[8];
#pragma unroll
        for (int i = 0; i < 4; i++) {
            float4 v = *(const float4*)(aSrc + i * 4);
            pa[i * 2] = h2u(v.x, v.y); pa[i * 2 + 1] = h2u(v.z, v.w);
            float4 w = *(const float4*)(bSrc + i * 4);
            pb[i * 2] = h2u(w.x, w.y); pb[i * 2 + 1] = h2u(w.z, w.w);
        }
        *(uint4*)&As[0][aRow * A_STR + aHalf]     = *(uint4*)pa;
        *(uint4*)&As[0][aRow * A_STR + aHalf + 8] = *(uint4*)(pa + 4);
        *(uint4*)&Bs[0][bRow * B_STR + bHalf]     = *(uint4*)pb;
        *(uint4*)&Bs[0][bRow * B_STR + bHalf + 8] = *(uint4*)(pb + 4);
    }
    __syncthreads();

    int nk = K >> 5;
    int buf = 0;
    for (int kt = 0; kt < nk; kt++) {
        uint32_t pa[8], pb[8];
        if (kt + 1 < nk) {
            const float* ap = aSrc + (size_t)(kt + 1) * 32;
            const float* bp = bSrc + (size_t)(kt + 1) * 32 * N;
#pragma unroll
            for (int i = 0; i < 4; i++) {
                float4 v = *(const float4*)(ap + i * 4);
                pa[i * 2] = h2u(v.x, v.y); pa[i * 2 + 1] = h2u(v.z, v.w);
                float4 w = *(const float4*)(bp + i * 4);
                pb[i * 2] = h2u(w.x, w.y); pb[i * 2 + 1] = h2u(w.z, w.w);
            }
        }
        uint32_t aBase = smem_u32(&As[buf][0]);
        uint32_t bBase = smem_u32(&Bs[buf][0]);
#pragma unroll
        for (int kk = 0; kk < 2; kk++) {
            uint32_t af[4][4], bf[2][4];
#pragma unroll
            for (int mt = 0; mt < 4; mt++) {
                uint32_t addr = aBase +
                    ((wRow + mt * 16 + (lane & 15)) * A_STR + kk * 16 + (lane >> 4) * 8) * 2;
                ldsm4(af[mt], addr);
            }
#pragma unroll
            for (int nt2 = 0; nt2 < 2; nt2++) {
                int krow = kk * 16 + (lane & 7) + (((lane >> 3) & 1) << 3);
                int ncol = wCol + nt2 * 16 + (((lane >> 4) & 1) << 3);
                ldsm4t(bf[nt2], bBase + (krow * B_STR + ncol) * 2);
            }
#pragma unroll
            for (int mt = 0; mt < 4; mt++)
#pragma unroll
                for (int nt2 = 0; nt2 < 2; nt2++) {
                    mma_f16(acc[mt][nt2 * 2 + 0], af[mt], &bf[nt2][0]);
                    mma_f16(acc[mt][nt2 * 2 + 1], af[mt], &bf[nt2][2]);
                }
        }
        if (kt + 1 < nk) {
            int w = buf ^ 1;
            __syncthreads();
            *(uint4*)&As[w][aRow * A_STR + aHalf]     = *(uint4*)pa;
            *(uint4*)&As[w][aRow * A_STR + aHalf + 8] = *(uint4*)(pa + 4);
            *(uint4*)&Bs[w][bRow * B_STR + bHalf]     = *(uint4*)pb;
            *(uint4*)&Bs[w][bRow * B_STR + bHalf + 8] = *(uint4*)(pb + 4);
            __syncthreads();
            buf = w;
        }
    }

    // epilogue: lane holds rows (base+g, +8), cols (cbase+2t, +1)
    int g = lane >> 2, t = lane & 3;
#pragma unroll
    for (int mt = 0; mt < 4; mt++) {
#pragma unroll
        for (int half = 0; half < 2; half++) {
            int m = m0 + wRow + mt * 16 + g + half * 8;
            if (m >= Mc) continue;
#pragma unroll
            for (int nt = 0; nt < 4; nt++) {
                int c = n0 + wCol + nt * 8 + 2 * t;
                float v0 = acc[mt][nt][half * 2 + 0];
                float v1 = acc[mt][nt][half * 2 + 1];
                float* crow = C + (size_t)m * N + c;
                if (EPI == EPI_STORE) {
                    if (bias) { v0 += bias[c]; v1 += bias[c + 1]; }
                    crow[0] = v0; crow[1] = v1;
                } else if (EPI == EPI_SILU_MUL) {
                    float g0 = crow[0], g1 = crow[1];
                    crow[0] = (g0 / (1.f + __expf(-g0))) * v0;
                    crow[1] = (g1 / (1.f + __expf(-g1))) * v1;
                } else if (EPI == EPI_ADD_RES) {
                    const float* rrow = res + (size_t)m * N + c;
                    crow[0] = rrow[0] + v0; crow[1] = rrow[1] + v1;
                } else if (EPI == EPI_FINAL) {
                    size_t idx = (size_t)m * N + c;
                    float sg = sig[m];
                    crow[0] = res[idx] + moe[idx] + sg * v0;
                    crow[1] = res[idx + 1] + moe[idx + 1] + sg * v1;
                }
            }
        }
    }
}

// ---------------- router ----------------
__global__ __launch_bounds__(256) void k_router(const float* __restrict__ h,
                                                const float* __restrict__ gw,
                                                float* __restrict__ logits_out,
                                                float* __restrict__ wout,
                                                int* __restrict__ cnt,
                                                int* __restrict__ rows,
                                                int* __restrict__ posOut) {
    int t = blockIdx.x, tid = threadIdx.x;
    const float* hr = h + (size_t)t * HD;
    float p[NE];
#pragma unroll
    for (int e = 0; e < NE; e++) p[e] = 0.f;
    for (int i = tid; i < HD; i += 256) {
        float hv = hr[i];
        const float* g = gw + (size_t)i * NE;
#pragma unroll
        for (int e = 0; e < NE; e++) p[e] += hv * g[e];
    }
    for (int off = 16; off; off >>= 1)
#pragma unroll
        for (int e = 0; e < NE; e++) p[e] += __shfl_down_sync(0xFFFFFFFFu, p[e], off);
    __shared__ float smr[8][NE];
    int w = tid >> 5;
    if ((tid & 31) == 0)
#pragma unroll
        for (int e = 0; e < NE; e++) smr[w][e] = p[e];
    __syncthreads();
    if (tid == 0) {
        float l[NE];
#pragma unroll
        for (int e = 0; e < NE; e++) {
            float s = 0.f;
            for (int ww = 0; ww < 8; ww++) s += smr[ww][e];
            l[e] = s;
            logits_out[(size_t)t * NE + e] = s;
        }
        float mx = l[0];
#pragma unroll
        for (int e = 1; e < NE; e++) mx = fmaxf(mx, l[e]);
        float den = 0.f, r[NE];
#pragma unroll
        for (int e = 0; e < NE; e++) { r[e] = expf(l[e] - mx); den += r[e]; }
#pragma unroll
        for (int e = 0; e < NE; e++) r[e] /= den;
        bool used[NE];
        float wrow[NE];
#pragma unroll
        for (int e = 0; e < NE; e++) { used[e] = false; wrow[e] = 0.f; }
        for (int kk = 0; kk < NTOP; kk++) {
            int bi = -1; float bv = -1.f;
            for (int e = 0; e < NE; e++)
                if (!used[e] && r[e] > bv) { bv = r[e]; bi = e; }
            used[bi] = true;
            wrow[bi] = bv;
            int pos = atomicAdd(&cnt[bi], 1);
            rows[bi * SQ + pos] = t;
            posOut[t * NE + bi] = pos;
        }
#pragma unroll
        for (int e = 0; e < NE; e++) wout[t * NE + e] = wrow[e];
    }
}

// ---------------- shared gate ----------------
__global__ __launch_bounds__(256) void k_sgate(const float* __restrict__ h,
                                               const float* __restrict__ sgw,
                                               float* __restrict__ sig) {
    int t = blockIdx.x, tid = threadIdx.x;
    const float* hr = h + (size_t)t * HD;
    float s = 0.f;
    for (int i = tid; i < HD; i += 256) s += hr[i] * sgw[i];
    for (int off = 16; off; off >>= 1) s += __shfl_down_sync(0xFFFFFFFFu, s, off);
    __shared__ float red[8];
    if ((tid & 31) == 0) red[tid >> 5] = s;
    __syncthreads();
    if (tid == 0) {
        float tot = 0.f;
        for (int i = 0; i < 8; i++) tot += red[i];
        sig[t] = 1.f / (1.f + expf(-tot));
    }
}

// ---------------- deterministic MoE combine ----------------
__global__ __launch_bounds__(256) void k_combine(const float* __restrict__ edown,
                                                 const float* __restrict__ w,
                                                 const int* __restrict__ pos,
                                                 float* __restrict__ moe) {
    int t = blockIdx.x, tid = threadIdx.x;
    float acc[8];
#pragma unroll
    for (int i = 0; i < 8; i++) acc[i] = 0.f;
    for (int e = 0; e < NE; e++) {
        float wv = w[t * NE + e];
        if (wv != 0.f) {
            const float* src = edown + (size_t)e * SQ * HD + (size_t)pos[t * NE + e] * HD;
#pragma unroll
            for (int i = 0; i < 8; i++) acc[i] += wv * src[tid + i * 256];
        }
    }
    float* dst = moe + (size_t)t * HD;
#pragma unroll
    for (int i = 0; i < 8; i++) dst[tid + i * 256] = acc[i];
}

// ---------------- launch ----------------
extern "C" void kernel_launch(void* const* d_in, const int* in_sizes, int n_in,
                              void* d_out, int out_size) {
    const float* x     = (const float*)d_in[0];
    const float* ln1   = (const float*)d_in[1];
    const float* ln2   = (const float*)d_in[2];
    const float* wq    = (const float*)d_in[3];
    const float* bq    = (const float*)d_in[4];
    const float* wk    = (const float*)d_in[5];
    const float* bk    = (const float*)d_in[6];
    const float* wv    = (const float*)d_in[7];
    const float* bv    = (const float*)d_in[8];
    const float* wo    = (const float*)d_in[9];
    const float* gatew = (const float*)d_in[10];
    const float* eg    = (const float*)d_in[11];
    const float* eu    = (const float*)d_in[12];
    const float* ed    = (const float*)d_in[13];
    const float* sgw   = (const float*)d_in[14];
    const float* suw   = (const float*)d_in[15];
    const float* sdw   = (const float*)d_in[16];
    const float* sgate = (const float*)d_in[17];
    float* out = (float*)d_out;

    float *h, *q, *k, *v, *attn, *x1, *moe, *sh, *eup, *edown, *w, *sig;
    int *rows, *pos, *cnt;
    cudaGetSymbolAddress((void**)&h, g_h);
    cudaGetSymbolAddress((void**)&q, g_q);
    cudaGetSymbolAddress((void**)&k, g_k);
    cudaGetSymbolAddress((void**)&v, g_v);
    cudaGetSymbolAddress((void**)&attn, g_attn);
    cudaGetSymbolAddress((void**)&x1, g_x1);
    cudaGetSymbolAddress((void**)&moe, g_moe);
    cudaGetSymbolAddress((void**)&sh, g_sh);
    cudaGetSymbolAddress((void**)&eup, g_eup);
    cudaGetSymbolAddress((void**)&edown, g_edown);
    cudaGetSymbolAddress((void**)&w, g_w);
    cudaGetSymbolAddress((void**)&sig, g_sig);
    cudaGetSymbolAddress((void**)&rows, g_rows);
    cudaGetSymbolAddress((void**)&pos, g_pos);
    cudaGetSymbolAddress((void**)&cnt, g_cnt);

    cudaFuncSetAttribute(k_attn_mma, cudaFuncAttributeMaxDynamicSharedMemorySize, ATTN_SMEM);

    // 0. reset expert counters
    k_zero_cnt<<<1, 32>>>(cnt);

    // 1. ln1
    k_rmsnorm<<<SQ, 256>>>(x, ln1, h);

    // 2. qkv
    dim3 g16(HD / 128, SQ / 128);
    k_gemm<EPI_STORE, false, false><<<g16, 256>>>(h, wq, q, SQ, HD, HD, bq, nullptr, nullptr, nullptr, nullptr, nullptr, 0, 0, 0);
    k_gemm<EPI_STORE, false, false><<<g16, 256>>>(h, wk, k, SQ, HD, HD, bk, nullptr, nullptr, nullptr, nullptr, nullptr, 0, 0, 0);
    k_gemm<EPI_STORE, false, false><<<g16, 256>>>(h, wv, v, SQ, HD, HD, bv, nullptr, nullptr, nullptr, nullptr, nullptr, 0, 0, 0);

    // 3. rope
    k_rope<<<dim3(SQ, NHD), 64>>>(q, k);

    // 4. attention (tf32 tensor cores)
    k_attn_mma<<<dim3(SQ / 64, NHD), 128, ATTN_SMEM>>>(q, k, v, attn);

    // 5. x1 = x + attn @ wo
    k_gemm<EPI_ADD_RES, false, false><<<g16, 256>>>(attn, wo, x1, SQ, HD, HD, nullptr, x, nullptr, nullptr, nullptr, nullptr, 0, 0, 0);

    // 6. ln2
    k_rmsnorm<<<SQ, 256>>>(x1, ln2, h);

    // 7. router + shared gate
    k_router<<<SQ, 256>>>(h, gatew, out + (size_t)SQ * HD, w, cnt, rows, pos);
    k_sgate<<<SQ, 256>>>(h, sgate, sig);

    // 8. MoE experts (fused over experts via blockIdx.z)
    dim3 ge(IEX / 128, SQ / 128, NE);
    k_gemm<EPI_STORE, true, true><<<ge, 256>>>(h, eg, eup,
        SQ, IEX, HD, nullptr, nullptr, rows, cnt, nullptr, nullptr,
        0, (size_t)HD * IEX, (size_t)SQ * IEX);
    k_gemm<EPI_SILU_MUL, true, true><<<ge, 256>>>(h, eu, eup,
        SQ, IEX, HD, nullptr, nullptr, rows, cnt, nullptr, nullptr,
        0, (size_t)HD * IEX, (size_t)SQ * IEX);
    dim3 gd(HD / 128, SQ / 128, NE);
    k_gemm<EPI_STORE, false, true><<<gd, 256>>>(eup, ed, edown,
        SQ, HD, IEX, nullptr, nullptr, rows, cnt, nullptr, nullptr,
        (size_t)SQ * IEX, (size_t)IEX * HD, (size_t)SQ * HD);

    // 8b. combine
    k_combine<<<SQ, 256>>>(edown, w, pos, moe);

    // 9. shared expert
    dim3 gs(ISH / 128, SQ / 128);
    k_gemm<EPI_STORE, false, false><<<gs, 256>>>(h, sgw, sh, SQ, ISH, HD, nullptr, nullptr, nullptr, nullptr, nullptr, nullptr, 0, 0, 0);
    k_gemm<EPI_SILU_MUL, false, false><<<gs, 256>>>(h, suw, sh, SQ, ISH, HD, nullptr, nullptr, nullptr, nullptr, nullptr, nullptr, 0, 0, 0);

    // 10. final
    k_gemm<EPI_FINAL, false, false><<<g16, 256>>>(sh, sdw, out, SQ, HD, ISH, nullptr, x1, nullptr, nullptr, sig, moe, 0, 0, 0);
}

// round 14
// speedup vs baseline: 7.2710x; 2.3443x over previous
#include <cuda_runtime.h>
#include <cuda_fp16.h>
#include <math.h>
#include <stdint.h>

// ---------------- problem constants ----------------
#define SQ 2048
#define HD 2048
#define NHD 16
#define DH 128
#define NE 8
#define NTOP 4
#define IEX 1408
#define ISH 5632

// ---------------- scratch ----------------
__device__ float g_h[SQ * HD];
__device__ float g_q[SQ * HD];
__device__ float g_k[SQ * HD];
__device__ float g_v[SQ * HD];
__device__ float g_x1[SQ * HD];
__device__ float g_moe[SQ * HD];
__device__ float g_sh[SQ * ISH];
__device__ float g_eup[NE * SQ * IEX];
__device__ float g_edown[NE * SQ * HD];
__device__ float g_w[SQ * NE];
__device__ float g_sig[SQ];
__device__ int   g_rows[NE * SQ];
__device__ int   g_pos[SQ * NE];
__device__ int   g_cnt[NE];
// fp16 mirrors
__device__ __half g_h16[SQ * HD];
__device__ __half g_attn16[SQ * HD];
__device__ __half g_sh16[SQ * ISH];
__device__ __half g_eup16[NE * SQ * IEX];
__device__ __half g_wq16[HD * HD];
__device__ __half g_wk16[HD * HD];
__device__ __half g_wv16[HD * HD];
__device__ __half g_wo16[HD * HD];
__device__ __half g_eg16[NE * HD * IEX];
__device__ __half g_eu16[NE * HD * IEX];
__device__ __half g_ed16[NE * IEX * HD];
__device__ __half g_sg16[HD * ISH];
__device__ __half g_su16[HD * ISH];
__device__ __half g_sd16[ISH * HD];

__global__ void k_zero_cnt(int* cnt) {
    if (threadIdx.x < NE) cnt[threadIdx.x] = 0;
}

__device__ __forceinline__ uint32_t h2u(float a, float b) {
    __half2 h = __floats2half2_rn(a, b);
    return *(uint32_t*)&h;
}

// ---------------- fp32 -> fp16 convert (8 elts/thread) ----------------
__global__ __launch_bounds__(256) void k_cvt(const float* __restrict__ s,
                                             __half* __restrict__ d, int n8) {
    int i = blockIdx.x * 256 + threadIdx.x;
    if (i < n8) {
        const float4* sp = (const float4*)s + (size_t)i * 2;
        float4 a = sp[0], b = sp[1];
        uint32_t p[4] = {h2u(a.x, a.y), h2u(a.z, a.w), h2u(b.x, b.y), h2u(b.z, b.w)};
        *(uint4*)(d + (size_t)i * 8) = *(uint4*)p;
    }
}

// ---------------- RMSNorm (dual fp32 + fp16 output) ----------------
__global__ __launch_bounds__(256) void k_rmsnorm(const float* __restrict__ x,
                                                 const float* __restrict__ w,
                                                 float* __restrict__ out,
                                                 __half* __restrict__ out16) {
    int r = blockIdx.x, tid = threadIdx.x;
    const float* xr = x + (size_t)r * HD;
    float s = 0.f;
    for (int i = tid; i < HD; i += 256) { float v = xr[i]; s += v * v; }
    for (int o = 16; o; o >>= 1) s += __shfl_down_sync(0xFFFFFFFFu, s, o);
    __shared__ float red[8];
    __shared__ float rs_sh;
    if ((tid & 31) == 0) red[tid >> 5] = s;
    __syncthreads();
    if (tid == 0) {
        float t = 0.f;
        for (int i = 0; i < 8; i++) t += red[i];
        rs_sh = rsqrtf(t / (float)HD + 1e-6f);
    }
    __syncthreads();
    float rs = rs_sh;
    float* orow = out + (size_t)r * HD;
    __half* hrow = out16 + (size_t)r * HD;
    for (int i = tid; i < HD; i += 256) {
        float v = w[i] * xr[i] * rs;
        orow[i] = v;
        hrow[i] = __float2half(v);
    }
}

// ---------------- RoPE ----------------
__global__ void k_rope(float* __restrict__ q, float* __restrict__ k) {
    int s = blockIdx.x, h = blockIdx.y, d = threadIdx.x;
    float inv = 1.0f / powf(1.0e6f, (float)d / 64.0f);
    float ang = (float)s * inv;
    float sn, c;
    sincosf(ang, &sn, &c);
    size_t b = (size_t)s * HD + (size_t)h * DH;
    float q1 = q[b + d], q2 = q[b + d + 64];
    q[b + d]      = q1 * c - q2 * sn;
    q[b + d + 64] = q2 * c + q1 * sn;
    float k1 = k[b + d], k2 = k[b + d + 64];
    k[b + d]      = k1 * c - k2 * sn;
    k[b + d + 64] = k2 * c + k1 * sn;
}

// ---------------- tf32 mma helpers (attention) ----------------
__device__ __forceinline__ uint32_t f2tf(float f) {
    uint32_t u;
    asm("cvt.rna.tf32.f32 %0, %1;" : "=r"(u) : "f"(f));
    return u;
}
__device__ __forceinline__ void mma_tf32(float* c, const uint32_t* a, const uint32_t* b) {
    asm volatile(
        "mma.sync.aligned.m16n8k8.row.col.f32.tf32.tf32.f32 "
        "{%0,%1,%2,%3}, {%4,%5,%6,%7}, {%8,%9}, {%0,%1,%2,%3};"
        : "+f"(c[0]), "+f"(c[1]), "+f"(c[2]), "+f"(c[3])
        : "r"(a[0]), "r"(a[1]), "r"(a[2]), "r"(a[3]), "r"(b[0]), "r"(b[1]));
}

// ---------------- flash attention (tf32 tensor cores, causal; fp16 out) ----
#define QSTR 132
#define KSTR 132
#define VSTR 136
#define PSTR 68
#define ATTN_SMEM ((64 * QSTR + 64 * VSTR + 64 * PSTR) * 4)

__global__ __launch_bounds__(128) void k_attn_mma(const float* __restrict__ Q,
                                                  const float* __restrict__ Km,
                                                  const float* __restrict__ Vm,
                                                  __half* __restrict__ O16) {
    extern __shared__ float sm[];
    float* Qs  = sm;
    float* KVs = sm + 64 * QSTR;
    float* Ps  = KVs + 64 * VSTR;

    int qt = (int)gridDim.x - 1 - (int)blockIdx.x;
    int h = blockIdx.y;
    int tid = threadIdx.x, warp = tid >> 5, lane = tid & 31;
    int g = lane >> 2, t = lane & 3;
    int qs = qt * 64;
    int r0 = warp * 16 + g;

    for (int idx = tid; idx < 64 * 32; idx += 128) {
        int r = idx >> 5, c4 = (idx & 31) * 4;
        float4 qv = *(const float4*)&Q[(size_t)(qs + r) * HD + (size_t)h * DH + c4];
        uint32_t* d = (uint32_t*)&Qs[r * QSTR + c4];
        d[0] = f2tf(qv.x); d[1] = f2tf(qv.y); d[2] = f2tf(qv.z); d[3] = f2tf(qv.w);
    }

    float oacc[16][4];
#pragma unroll
    for (int i = 0; i < 16; i++) { oacc[i][0] = oacc[i][1] = oacc[i][2] = oacc[i][3] = 0.f; }
    float m0 = -INFINITY, m1 = -INFINITY, l0 = 0.f, l1 = 0.f;
    const float scale = 0.08838834764831845f;

    const uint32_t* Qu = (const uint32_t*)Qs;
    const uint32_t* KVu = (const uint32_t*)KVs;
    uint32_t* Pu = (uint32_t*)Ps;

    for (int kt = 0; kt <= qt; kt++) {
        int ks = kt * 64;
        __syncthreads();
        for (int idx = tid; idx < 64 * 32; idx += 128) {
            int r = idx >> 5, c4 = (idx & 31) * 4;
            float4 kv = *(const float4*)&Km[(size_t)(ks + r) * HD + (size_t)h * DH + c4];
            uint32_t* d = (uint32_t*)&KVs[r * KSTR + c4];
            d[0] = f2tf(kv.x); d[1] = f2tf(kv.y); d[2] = f2tf(kv.z); d[3] = f2tf(kv.w);
        }
        __syncthreads();

        float sacc[8][4];
#pragma unroll
        for (int nt = 0; nt < 8; nt++) sacc[nt][0] = sacc[nt][1] = sacc[nt][2] = sacc[nt][3] = 0.f;
#pragma unroll
        for (int kk = 0; kk < 16; kk++) {
            uint32_t af[4];
            af[0] = Qu[r0 * QSTR + kk * 8 + t];
            af[1] = Qu[(r0 + 8) * QSTR + kk * 8 + t];
            af[2] = Qu[r0 * QSTR + kk * 8 + t + 4];
            af[3] = Qu[(r0 + 8) * QSTR + kk * 8 + t + 4];
#pragma unroll
            for (int nt = 0; nt < 8; nt++) {
                uint32_t bf[2];
                bf[0] = KVu[(nt * 8 + g) * KSTR + kk * 8 + t];
                bf[1] = KVu[(nt * 8 + g) * KSTR + kk * 8 + t + 4];
                mma_tf32(sacc[nt], af, bf);
            }
        }

        float mx0 = -INFINITY, mx1 = -INFINITY;
#pragma unroll
        for (int nt = 0; nt < 8; nt++) {
            sacc[nt][0] *= scale; sacc[nt][1] *= scale;
            sacc[nt][2] *= scale; sacc[nt][3] *= scale;
            if (kt == qt) {
                int col = nt * 8 + 2 * t;
                if (col     > r0)     sacc[nt][0] = -INFINITY;
                if (col + 1 > r0)     sacc[nt][1] = -INFINITY;
                if (col     > r0 + 8) sacc[nt][2] = -INFINITY;
                if (col + 1 > r0 + 8) sacc[nt][3] = -INFINITY;
            }
            mx0 = fmaxf(mx0, fmaxf(sacc[nt][0], sacc[nt][1]));
            mx1 = fmaxf(mx1, fmaxf(sacc[nt][2], sacc[nt][3]));
        }
        mx0 = fmaxf(mx0, __shfl_xor_sync(0xFFFFFFFFu, mx0, 1));
        mx0 = fmaxf(mx0, __shfl_xor_sync(0xFFFFFFFFu, mx0, 2));
        mx1 = fmaxf(mx1, __shfl_xor_sync(0xFFFFFFFFu, mx1, 1));
        mx1 = fmaxf(mx1, __shfl_xor_sync(0xFFFFFFFFu, mx1, 2));

        float mn0 = fmaxf(m0, mx0), mn1 = fmaxf(m1, mx1);
        float a0 = __expf(m0 - mn0), a1 = __expf(m1 - mn1);
        float ls0 = 0.f, ls1 = 0.f;
#pragma unroll
        for (int nt = 0; nt < 8; nt++) {
            float p00 = __expf(sacc[nt][0] - mn0);
            float p01 = __expf(sacc[nt][1] - mn0);
            float p10 = __expf(sacc[nt][2] - mn1);
            float p11 = __expf(sacc[nt][3] - mn1);
            ls0 += p00 + p01;
            ls1 += p10 + p11;
            uint32_t* pd0 = &Pu[r0 * PSTR + nt * 8 + 2 * t];
            pd0[0] = f2tf(p00); pd0[1] = f2tf(p01);
            uint32_t* pd1 = &Pu[(r0 + 8) * PSTR + nt * 8 + 2 * t];
            pd1[0] = f2tf(p10); pd1[1] = f2tf(p11);
        }
        ls0 += __shfl_xor_sync(0xFFFFFFFFu, ls0, 1);
        ls0 += __shfl_xor_sync(0xFFFFFFFFu, ls0, 2);
        ls1 += __shfl_xor_sync(0xFFFFFFFFu, ls1, 1);
        ls1 += __shfl_xor_sync(0xFFFFFFFFu, ls1, 2);
        l0 = l0 * a0 + ls0;
        l1 = l1 * a1 + ls1;
        m0 = mn0; m1 = mn1;
#pragma unroll
        for (int nt = 0; nt < 16; nt++) {
            oacc[nt][0] *= a0; oacc[nt][1] *= a0;
            oacc[nt][2] *= a1; oacc[nt][3] *= a1;
        }
        __syncthreads();

        for (int idx = tid; idx < 64 * 32; idx += 128) {
            int r = idx >> 5, c4 = (idx & 31) * 4;
            float4 vv = *(const float4*)&Vm[(size_t)(ks + r) * HD + (size_t)h * DH + c4];
            uint32_t* d = (uint32_t*)&KVs[r * VSTR + c4];
            d[0] = f2tf(vv.x); d[1] = f2tf(vv.y); d[2] = f2tf(vv.z); d[3] = f2tf(vv.w);
        }
        __syncthreads();

#pragma unroll
        for (int kk = 0; kk < 8; kk++) {
            uint32_t af[4];
            af[0] = Pu[r0 * PSTR + kk * 8 + t];
            af[1] = Pu[(r0 + 8) * PSTR + kk * 8 + t];
            af[2] = Pu[r0 * PSTR + kk * 8 + t + 4];
            af[3] = Pu[(r0 + 8) * PSTR + kk * 8 + t + 4];
#pragma unroll
            for (int nt = 0; nt < 16; nt++) {
                uint32_t bf[2];
                bf[0] = KVu[(kk * 8 + t) * VSTR + nt * 8 + g];
                bf[1] = KVu[(kk * 8 + t + 4) * VSTR + nt * 8 + g];
                mma_tf32(oacc[nt], af, bf);
            }
        }
    }

    float inv0 = 1.f / l0, inv1 = 1.f / l1;
#pragma unroll
    for (int nt = 0; nt < 16; nt++) {
        int d = nt * 8 + 2 * t;
        size_t b0 = (size_t)(qs + r0) * HD + (size_t)h * DH + d;
        size_t b1 = (size_t)(qs + r0 + 8) * HD + (size_t)h * DH + d;
        *(__half2*)&O16[b0] = __floats2half2_rn(oacc[nt][0] * inv0, oacc[nt][1] * inv0);
        *(__half2*)&O16[b1] = __floats2half2_rn(oacc[nt][2] * inv1, oacc[nt][3] * inv1);
    }
}

// ================= fp16 HMMA GEMM, cp.async 3-stage pipeline =================
// C = A(MxK) @ B(KxN); A,B fp16 gmem; fp32 accum; CTA 128x128, BK=32.
enum { EPI_STORE = 0, EPI_SILU_MUL = 1, EPI_ADD_RES = 2, EPI_FINAL = 3 };

#define A_STR 40
#define B_STR 136
#define STG 3
#define STAGE_H (128 * A_STR + 32 * B_STR)          // halves per stage
#define GEMM_SMEM (STG * STAGE_H * 2)               // 56832 bytes

__device__ __forceinline__ uint32_t smem_u32(const void* p) {
    uint32_t a;
    asm("{ .reg .u64 t; cvta.to.shared.u64 t, %1; cvt.u32.u64 %0, t; }" : "=r"(a) : "l"(p));
    return a;
}
__device__ __forceinline__ void cpa16(uint32_t saddr, const void* gaddr) {
    asm volatile("cp.async.cg.shared.global [%0], [%1], 16;" :: "r"(saddr), "l"(gaddr));
}
__device__ __forceinline__ void ldsm4(uint32_t* r, uint32_t addr) {
    asm volatile("ldmatrix.sync.aligned.m8n8.x4.shared.b16 {%0,%1,%2,%3}, [%4];"
                 : "=r"(r[0]), "=r"(r[1]), "=r"(r[2]), "=r"(r[3]) : "r"(addr));
}
__device__ __forceinline__ void ldsm4t(uint32_t* r, uint32_t addr) {
    asm volatile("ldmatrix.sync.aligned.m8n8.x4.trans.shared.b16 {%0,%1,%2,%3}, [%4];"
                 : "=r"(r[0]), "=r"(r[1]), "=r"(r[2]), "=r"(r[3]) : "r"(addr));
}
__device__ __forceinline__ void mma_f16(float* c, const uint32_t* a, const uint32_t* b) {
    asm volatile(
        "mma.sync.aligned.m16n8k16.row.col.f32.f16.f16.f32 "
        "{%0,%1,%2,%3}, {%4,%5,%6,%7}, {%8,%9}, {%0,%1,%2,%3};"
        : "+f"(c[0]), "+f"(c[1]), "+f"(c[2]), "+f"(c[3])
        : "r"(a[0]), "r"(a[1]), "r"(a[2]), "r"(a[3]), "r"(b[0]), "r"(b[1]));
}

template <int EPI, bool GATHER, bool FUSEZ>
__global__ __launch_bounds__(256) void k_gemm(
    const __half* __restrict__ A, const __half* __restrict__ B,
    float* __restrict__ C, __half* __restrict__ Ch,
    int M, int N, int K,
    const float* __restrict__ bias,
    const float* __restrict__ res,
    const int* __restrict__ rowIdx, const int* __restrict__ rowCnt,
    const float* __restrict__ sig, const float* __restrict__ moe,
    size_t zsA, size_t zsB, size_t zsC) {
    if (FUSEZ) {
        int z = blockIdx.z;
        A += (size_t)z * zsA; B += (size_t)z * zsB;
        C += (size_t)z * zsC;
        if (Ch) Ch += (size_t)z * zsC;
        rowIdx += z * SQ; rowCnt += z;
    }
    int Mc = rowCnt ? *rowCnt : M;
    int m0 = blockIdx.y * 128;
    if (m0 >= Mc) return;
    int n0 = blockIdx.x * 128;

    extern __shared__ __half smh[];
    __shared__ int rowsSm[128];

    int tid = threadIdx.x;
    int warp = tid >> 5, lane = tid & 31;
    int wm = warp >> 2, wn = warp & 3;
    int wRow = wm * 64, wCol = wn * 32;

    if (tid < 128) {
        int m = m0 + tid; if (m > Mc - 1) m = Mc - 1;
        rowsSm[tid] = GATHER ? rowIdx[m] : m;
    }
    __syncthreads();

    float acc[4][4][4];
#pragma unroll
    for (int i = 0; i < 4; i++)
#pragma unroll
        for (int j = 0; j < 4; j++)
#pragma unroll
            for (int q = 0; q < 4; q++) acc[i][j][q] = 0.f;

    int nk = K >> 5;

    auto load_tile = [&](int kt, int s) {
        __half* As = smh + s * STAGE_H;
        __half* Bs = As + 128 * A_STR;
        int k0 = kt * 32;
#pragma unroll
        for (int i = 0; i < 2; i++) {
            int c = tid * 2 + i;
            int ar = c >> 2, aseg = c & 3;
            cpa16(smem_u32(As + ar * A_STR + aseg * 8),
                  A + (size_t)rowsSm[ar] * K + k0 + aseg * 8);
            int br = c >> 4, bseg = c & 15;
            cpa16(smem_u32(Bs + br * B_STR + bseg * 8),
                  B + (size_t)(k0 + br) * N + n0 + bseg * 8);
        }
    };

    load_tile(0, 0);
    asm volatile("cp.async.commit_group;");
    load_tile(1, 1);
    asm volatile("cp.async.commit_group;");

    int buf = 0;
    for (int kt = 0; kt < nk; kt++) {
        asm volatile("cp.async.wait_group %0;" :: "n"(1));
        __syncthreads();
        if (kt + 2 < nk) load_tile(kt + 2, (buf + 2 >= STG) ? buf + 2 - STG : buf + 2);
        asm volatile("cp.async.commit_group;");

        uint32_t aBase = smem_u32(smh + buf * STAGE_H);
        uint32_t bBase = aBase + 128 * A_STR * 2;
#pragma unroll
        for (int kk = 0; kk < 2; kk++) {
            uint32_t af[4][4], bf[2][4];
#pragma unroll
            for (int mt = 0; mt < 4; mt++) {
                uint32_t addr = aBase +
                    ((wRow + mt * 16 + (lane & 15)) * A_STR + kk * 16 + (lane >> 4) * 8) * 2;
                ldsm4(af[mt], addr);
            }
#pragma unroll
            for (int nt2 = 0; nt2 < 2; nt2++) {
                int krow = kk * 16 + (lane & 7) + (((lane >> 3) & 1) << 3);
                int ncol = wCol + nt2 * 16 + (((lane >> 4) & 1) << 3);
                ldsm4t(bf[nt2], bBase + (krow * B_STR + ncol) * 2);
            }
#pragma unroll
            for (int mt = 0; mt < 4; mt++)
#pragma unroll
                for (int nt2 = 0; nt2 < 2; nt2++) {
                    mma_f16(acc[mt][nt2 * 2 + 0], af[mt], &bf[nt2][0]);
                    mma_f16(acc[mt][nt2 * 2 + 1], af[mt], &bf[nt2][2]);
                }
        }
        buf = (buf + 1 == STG) ? 0 : buf + 1;
    }

    // epilogue
    int g = lane >> 2, t = lane & 3;
#pragma unroll
    for (int mt = 0; mt < 4; mt++) {
#pragma unroll
        for (int half = 0; half < 2; half++) {
            int m = m0 + wRow + mt * 16 + g + half * 8;
            if (m >= Mc) continue;
#pragma unroll
            for (int nt = 0; nt < 4; nt++) {
                int c = n0 + wCol + nt * 8 + 2 * t;
                float v0 = acc[mt][nt][half * 2 + 0];
                float v1 = acc[mt][nt][half * 2 + 1];
                size_t idx = (size_t)m * N + c;
                if (EPI == EPI_STORE) {
                    if (bias) { v0 += bias[c]; v1 += bias[c + 1]; }
                    C[idx] = v0; C[idx + 1] = v1;
                } else if (EPI == EPI_SILU_MUL) {
                    float g0 = C[idx], g1 = C[idx + 1];
                    float r0 = (g0 / (1.f + __expf(-g0))) * v0;
                    float r1 = (g1 / (1.f + __expf(-g1))) * v1;
                    *(__half2*)&Ch[idx] = __floats2half2_rn(r0, r1);
                } else if (EPI == EPI_ADD_RES) {
                    C[idx] = res[idx] + v0; C[idx + 1] = res[idx + 1] + v1;
                } else if (EPI == EPI_FINAL) {
                    float sg = sig[m];
                    C[idx] = res[idx] + moe[idx] + sg * v0;
                    C[idx + 1] = res[idx + 1] + moe[idx + 1] + sg * v1;
                }
            }
        }
    }
}

// ---------------- router ----------------
__global__ __launch_bounds__(256) void k_router(const float* __restrict__ h,
                                                const float* __restrict__ gw,
                                                float* __restrict__ logits_out,
                                                float* __restrict__ wout,
                                                int* __restrict__ cnt,
                                                int* __restrict__ rows,
                                                int* __restrict__ posOut) {
    int t = blockIdx.x, tid = threadIdx.x;
    const float* hr = h + (size_t)t * HD;
    float p[NE];
#pragma unroll
    for (int e = 0; e < NE; e++) p[e] = 0.f;
    for (int i = tid; i < HD; i += 256) {
        float hv = hr[i];
        const float* g = gw + (size_t)i * NE;
#pragma unroll
        for (int e = 0; e < NE; e++) p[e] += hv * g[e];
    }
    for (int off = 16; off; off >>= 1)
#pragma unroll
        for (int e = 0; e < NE; e++) p[e] += __shfl_down_sync(0xFFFFFFFFu, p[e], off);
    __shared__ float smr[8][NE];
    int w = tid >> 5;
    if ((tid & 31) == 0)
#pragma unroll
        for (int e = 0; e < NE; e++) smr[w][e] = p[e];
    __syncthreads();
    if (tid == 0) {
        float l[NE];
#pragma unroll
        for (int e = 0; e < NE; e++) {
            float s = 0.f;
            for (int ww = 0; ww < 8; ww++) s += smr[ww][e];
            l[e] = s;
            logits_out[(size_t)t * NE + e] = s;
        }
        float mx = l[0];
#pragma unroll
        for (int e = 1; e < NE; e++) mx = fmaxf(mx, l[e]);
        float den = 0.f, r[NE];
#pragma unroll
        for (int e = 0; e < NE; e++) { r[e] = expf(l[e] - mx); den += r[e]; }
#pragma unroll
        for (int e = 0; e < NE; e++) r[e] /= den;
        bool used[NE];
        float wrow[NE];
#pragma unroll
        for (int e = 0; e < NE; e++) { used[e] = false; wrow[e] = 0.f; }
        for (int kk = 0; kk < NTOP; kk++) {
            int bi = -1; float bv = -1.f;
            for (int e = 0; e < NE; e++)
                if (!used[e] && r[e] > bv) { bv = r[e]; bi = e; }
            used[bi] = true;
            wrow[bi] = bv;
            int pos = atomicAdd(&cnt[bi], 1);
            rows[bi * SQ + pos] = t;
            posOut[t * NE + bi] = pos;
        }
#pragma unroll
        for (int e = 0; e < NE; e++) wout[t * NE + e] = wrow[e];
    }
}

// ---------------- shared gate ----------------
__global__ __launch_bounds__(256) void k_sgate(const float* __restrict__ h,
                                               const float* __restrict__ sgw,
                                               float* __restrict__ sig) {
    int t = blockIdx.x, tid = threadIdx.x;
    const float* hr = h + (size_t)t * HD;
    float s = 0.f;
    for (int i = tid; i < HD; i += 256) s += hr[i] * sgw[i];
    for (int off = 16; off; off >>= 1) s += __shfl_down_sync(0xFFFFFFFFu, s, off);
    __shared__ float red[8];
    if ((tid & 31) == 0) red[tid >> 5] = s;
    __syncthreads();
    if (tid == 0) {
        float tot = 0.f;
        for (int i = 0; i < 8; i++) tot += red[i];
        sig[t] = 1.f / (1.f + expf(-tot));
    }
}

// ---------------- deterministic MoE combine ----------------
__global__ __launch_bounds__(256) void k_combine(const float* __restrict__ edown,
                                                 const float* __restrict__ w,
                                                 const int* __restrict__ pos,
                                                 float* __restrict__ moe) {
    int t = blockIdx.x, tid = threadIdx.x;
    float acc[8];
#pragma unroll
    for (int i = 0; i < 8; i++) acc[i] = 0.f;
    for (int e = 0; e < NE; e++) {
        float wv = w[t * NE + e];
        if (wv != 0.f) {
            const float* src = edown + (size_t)e * SQ * HD + (size_t)pos[t * NE + e] * HD;
#pragma unroll
            for (int i = 0; i < 8; i++) acc[i] += wv * src[tid + i * 256];
        }
    }
    float* dst = moe + (size_t)t * HD;
#pragma unroll
    for (int i = 0; i < 8; i++) dst[tid + i * 256] = acc[i];
}

// ---------------- launch ----------------
extern "C" void kernel_launch(void* const* d_in, const int* in_sizes, int n_in,
                              void* d_out, int out_size) {
    const float* x     = (const float*)d_in[0];
    const float* ln1   = (const float*)d_in[1];
    const float* ln2   = (const float*)d_in[2];
    const float* wq    = (const float*)d_in[3];
    const float* bq    = (const float*)d_in[4];
    const float* wk    = (const float*)d_in[5];
    const float* bk    = (const float*)d_in[6];
    const float* wv    = (const float*)d_in[7];
    const float* bv    = (const float*)d_in[8];
    const float* wo    = (const float*)d_in[9];
    const float* gatew = (const float*)d_in[10];
    const float* eg    = (const float*)d_in[11];
    const float* eu    = (const float*)d_in[12];
    const float* ed    = (const float*)d_in[13];
    const float* sgw   = (const float*)d_in[14];
    const float* suw   = (const float*)d_in[15];
    const float* sdw   = (const float*)d_in[16];
    const float* sgate = (const float*)d_in[17];
    float* out = (float*)d_out;

    float *h, *q, *k, *v, *x1, *moe, *sh, *eup, *edown, *w, *sig;
    int *rows, *pos, *cnt;
    __half *h16, *attn16, *sh16, *eup16;
    __half *wq16, *wk16, *wv16, *wo16, *eg16, *eu16, *ed16, *sg16, *su16, *sd16;
    cudaGetSymbolAddress((void**)&h, g_h);
    cudaGetSymbolAddress((void**)&q, g_q);
    cudaGetSymbolAddress((void**)&k, g_k);
    cudaGetSymbolAddress((void**)&v, g_v);
    cudaGetSymbolAddress((void**)&x1, g_x1);
    cudaGetSymbolAddress((void**)&moe, g_moe);
    cudaGetSymbolAddress((void**)&sh, g_sh);
    cudaGetSymbolAddress((void**)&eup, g_eup);
    cudaGetSymbolAddress((void**)&edown, g_edown);
    cudaGetSymbolAddress((void**)&w, g_w);
    cudaGetSymbolAddress((void**)&sig, g_sig);
    cudaGetSymbolAddress((void**)&rows, g_rows);
    cudaGetSymbolAddress((void**)&pos, g_pos);
    cudaGetSymbolAddress((void**)&cnt, g_cnt);
    cudaGetSymbolAddress((void**)&h16, g_h16);
    cudaGetSymbolAddress((void**)&attn16, g_attn16);
    cudaGetSymbolAddress((void**)&sh16, g_sh16);
    cudaGetSymbolAddress((void**)&eup16, g_eup16);
    cudaGetSymbolAddress((void**)&wq16, g_wq16);
    cudaGetSymbolAddress((void**)&wk16, g_wk16);
    cudaGetSymbolAddress((void**)&wv16, g_wv16);
    cudaGetSymbolAddress((void**)&wo16, g_wo16);
    cudaGetSymbolAddress((void**)&eg16, g_eg16);
    cudaGetSymbolAddress((void**)&eu16, g_eu16);
    cudaGetSymbolAddress((void**)&ed16, g_ed16);
    cudaGetSymbolAddress((void**)&sg16, g_sg16);
    cudaGetSymbolAddress((void**)&su16, g_su16);
    cudaGetSymbolAddress((void**)&sd16, g_sd16);

    cudaFuncSetAttribute(k_attn_mma, cudaFuncAttributeMaxDynamicSharedMemorySize, ATTN_SMEM);
    cudaFuncSetAttribute(k_gemm<EPI_STORE, false, false>, cudaFuncAttributeMaxDynamicSharedMemorySize, GEMM_SMEM);
    cudaFuncSetAttribute(k_gemm<EPI_ADD_RES, false, false>, cudaFuncAttributeMaxDynamicSharedMemorySize, GEMM_SMEM);
    cudaFuncSetAttribute(k_gemm<EPI_SILU_MUL, false, false>, cudaFuncAttributeMaxDynamicSharedMemorySize, GEMM_SMEM);
    cudaFuncSetAttribute(k_gemm<EPI_FINAL, false, false>, cudaFuncAttributeMaxDynamicSharedMemorySize, GEMM_SMEM);
    cudaFuncSetAttribute(k_gemm<EPI_STORE, true, true>, cudaFuncAttributeMaxDynamicSharedMemorySize, GEMM_SMEM);
    cudaFuncSetAttribute(k_gemm<EPI_SILU_MUL, true, true>, cudaFuncAttributeMaxDynamicSharedMemorySize, GEMM_SMEM);
    cudaFuncSetAttribute(k_gemm<EPI_STORE, false, true>, cudaFuncAttributeMaxDynamicSharedMemorySize, GEMM_SMEM);

    // 0. reset counters + weight conversions (idempotent, inside graph)
    k_zero_cnt<<<1, 32>>>(cnt);
    k_cvt<<<HD * HD / 2048, 256>>>(wq, wq16, HD * HD / 8);
    k_cvt<<<HD * HD / 2048, 256>>>(wk, wk16, HD * HD / 8);
    k_cvt<<<HD * HD / 2048, 256>>>(wv, wv16, HD * HD / 8);
    k_cvt<<<HD * HD / 2048, 256>>>(wo, wo16, HD * HD / 8);
    k_cvt<<<NE * HD * IEX / 2048, 256>>>(eg, eg16, NE * HD * IEX / 8);
    k_cvt<<<NE * HD * IEX / 2048, 256>>>(eu, eu16, NE * HD * IEX / 8);
    k_cvt<<<NE * IEX * HD / 2048, 256>>>(ed, ed16, NE * IEX * HD / 8);
    k_cvt<<<HD * ISH / 2048, 256>>>(sgw, sg16, HD * ISH / 8);
    k_cvt<<<HD * ISH / 2048, 256>>>(suw, su16, HD * ISH / 8);
    k_cvt<<<ISH * HD / 2048, 256>>>(sdw, sd16, ISH * HD / 8);

    // 1. ln1 (fp32 + fp16 out)
    k_rmsnorm<<<SQ, 256>>>(x, ln1, h, h16);

    // 2. qkv (fp16 in, fp32 out)
    dim3 g16(HD / 128, SQ / 128);
    k_gemm<EPI_STORE, false, false><<<g16, 256, GEMM_SMEM>>>(h16, wq16, q, nullptr, SQ, HD, HD, bq, nullptr, nullptr, nullptr, nullptr, nullptr, 0, 0, 0);
    k_gemm<EPI_STORE, false, false><<<g16, 256, GEMM_SMEM>>>(h16, wk16, k, nullptr, SQ, HD, HD, bk, nullptr, nullptr, nullptr, nullptr, nullptr, 0, 0, 0);
    k_gemm<EPI_STORE, false, false><<<g16, 256, GEMM_SMEM>>>(h16, wv16, v, nullptr, SQ, HD, HD, bv, nullptr, nullptr, nullptr, nullptr, nullptr, 0, 0, 0);

    // 3. rope
    k_rope<<<dim3(SQ, NHD), 64>>>(q, k);

    // 4. attention (fp16 output)
    k_attn_mma<<<dim3(SQ / 64, NHD), 128, ATTN_SMEM>>>(q, k, v, attn16);

    // 5. x1 = x + attn @ wo
    k_gemm<EPI_ADD_RES, false, false><<<g16, 256, GEMM_SMEM>>>(attn16, wo16, x1, nullptr, SQ, HD, HD, nullptr, x, nullptr, nullptr, nullptr, nullptr, 0, 0, 0);

    // 6. ln2
    k_rmsnorm<<<SQ, 256>>>(x1, ln2, h, h16);

    // 7. router (fp32 exact) + shared gate
    k_router<<<SQ, 256>>>(h, gatew, out + (size_t)SQ * HD, w, cnt, rows, pos);
    k_sgate<<<SQ, 256>>>(h, sgate, sig);

    // 8. MoE experts (fused over experts via blockIdx.z)
    dim3 ge(IEX / 128, SQ / 128, NE);
    k_gemm<EPI_STORE, true, true><<<ge, 256, GEMM_SMEM>>>(h16, eg16, eup, nullptr,
        SQ, IEX, HD, nullptr, nullptr, rows, cnt, nullptr, nullptr,
        0, (size_t)HD * IEX, (size_t)SQ * IEX);
    k_gemm<EPI_SILU_MUL, true, true><<<ge, 256, GEMM_SMEM>>>(h16, eu16, eup, eup16,
        SQ, IEX, HD, nullptr, nullptr, rows, cnt, nullptr, nullptr,
        0, (size_t)HD * IEX, (size_t)SQ * IEX);
    dim3 gd(HD / 128, SQ / 128, NE);
    k_gemm<EPI_STORE, false, true><<<gd, 256, GEMM_SMEM>>>(eup16, ed16, edown, nullptr,
        SQ, HD, IEX, nullptr, nullptr, rows, cnt, nullptr, nullptr,
        (size_t)SQ * IEX, (size_t)IEX * HD, (size_t)SQ * HD);

    // 8b. combine
    k_combine<<<SQ, 256>>>(edown, w, pos, moe);

    // 9. shared expert
    dim3 gs(ISH / 128, SQ / 128);
    k_gemm<EPI_STORE, false, false><<<gs, 256, GEMM_SMEM>>>(h16, sg16, sh, nullptr, SQ, ISH, HD, nullptr, nullptr, nullptr, nullptr, nullptr, nullptr, 0, 0, 0);
    k_gemm<EPI_SILU_MUL, false, false><<<gs, 256, GEMM_SMEM>>>(h16, su16, sh, sh16, SQ, ISH, HD, nullptr, nullptr, nullptr, nullptr, nullptr, nullptr, 0, 0, 0);

    // 10. final
    k_gemm<EPI_FINAL, false, false><<<g16, 256, GEMM_SMEM>>>(sh16, sd16, out, nullptr, SQ, HD, ISH, nullptr, x1, nullptr, nullptr, sig, moe, 0, 0, 0);
}